// round 13
// baseline (speedup 1.0000x reference)
#include <cuda_runtime.h>
#include <cuda_fp16.h>
#include <cfloat>
#include <cstdint>

#define DIM   256
#define KCB   8192
#define NTOT  32768
#define BM    128        // rescue tile (unchanged)
#define BN    128        // rescue tile (unchanged)
#define BMM   64         // main rows per CTA
#define BNN   64         // main codes per chunk
#define NQ    4
#define CPQ   32         // (KCB/NQ)/BNN
#define MARGIN 0.25f

#define XSTR  264
#define XS_BYTES (BMM * XSTR * 2)          // 33792
#define ES_BUF_BYTES (BNN * XSTR * 2)      // 33792
#define MAIN_SMEM (XS_BYTES + 2 * ES_BUF_BYTES)   // 101376 -> 2 CTAs/SM

// ---------------- device scratch ----------------
__device__ __align__(16) __half g_eh[KCB * DIM];
__device__ float g_esq[KCB];
__device__ int   g_best[NTOT];
__device__ int   g_flag[NTOT];
__device__ unsigned long long g_bestkey[NTOT];
__device__ int   g_nflag;
__device__ int   g_npair;
__device__ int   g_pairn[NTOT];
__device__ int2  g_pairc[NTOT];
__device__ float g_pb[NQ * NTOT];
__device__ float g_ps[NQ * NTOT];
__device__ float g_pt[NQ * NTOT];
__device__ int   g_pi1[NQ * NTOT];
__device__ int   g_pi2[NQ * NTOT];

extern __shared__ char dynsmem[];

__device__ __forceinline__ uint32_t smem_u32(const void* p) {
    uint32_t a;
    asm("{ .reg .u64 t; cvta.to.shared.u64 t, %1; cvt.u32.u64 %0, t; }" : "=r"(a) : "l"(p));
    return a;
}
__device__ __forceinline__ void cpa16(uint32_t dst, const void* src) {
    asm volatile("cp.async.cg.shared.global [%0], [%1], 16;" :: "r"(dst), "l"(src));
}
#define CP_COMMIT() asm volatile("cp.async.commit_group;" ::: "memory")
#define CP_WAIT1()  asm volatile("cp.async.wait_group 1;" ::: "memory")

__device__ __forceinline__ void ldmx4(uint32_t& r0, uint32_t& r1, uint32_t& r2, uint32_t& r3,
                                      uint32_t addr) {
    asm volatile("ldmatrix.sync.aligned.m8n8.x4.shared.b16 {%0,%1,%2,%3}, [%4];"
                 : "=r"(r0), "=r"(r1), "=r"(r2), "=r"(r3) : "r"(addr));
}
__device__ __forceinline__ void mma16816(float* c, const uint32_t* a, const uint32_t* b) {
    asm volatile("mma.sync.aligned.m16n8k16.row.col.f32.f16.f16.f32 "
                 "{%0,%1,%2,%3}, {%4,%5,%6,%7}, {%8,%9}, {%0,%1,%2,%3};"
                 : "+f"(c[0]), "+f"(c[1]), "+f"(c[2]), "+f"(c[3])
                 : "r"(a[0]), "r"(a[1]), "r"(a[2]), "r"(a[3]), "r"(b[0]), "r"(b[1]));
}
__device__ __forceinline__ unsigned long long mkkey(float f, int idx) {
    unsigned u = __float_as_uint(f);
    u = (u & 0x80000000u) ? ~u : (u | 0x80000000u);
    return ((unsigned long long)u << 32) | (unsigned)idx;
}
__device__ __forceinline__ void ins3(float v, int ix,
                                     float& b, float& s, float& t, int& ib, int& is_) {
    if (v < b)      { t = s; s = b; is_ = ib; b = v; ib = ix; }
    else if (v < s) { t = s; s = v; is_ = ix; }
    else if (v < t) { t = v; }
}

// ---------------------------------------------------------------------------
// convert embed fp32 -> fp16; reset counters
// ---------------------------------------------------------------------------
__global__ void split_kernel(const float* __restrict__ embed) {
    if (blockIdx.x == 0 && threadIdx.x == 0) { g_nflag = 0; g_npair = 0; }
    const int T2 = KCB * DIM / 4;
    int stride = gridDim.x * blockDim.x;
    for (int i = blockIdx.x * blockDim.x + threadIdx.x; i < T2; i += stride) {
        float4 v = ((const float4*)embed)[i];
        ((__half2*)g_eh)[2 * i]     = __floats2half2_rn(v.x, v.y);
        ((__half2*)g_eh)[2 * i + 1] = __floats2half2_rn(v.z, v.w);
    }
}

__global__ void esq_kernel(const float* __restrict__ embed) {
    int k = blockIdx.x, lane = threadIdx.x;
    const float4* row = (const float4*)(embed + (size_t)k * DIM);
    float s = 0.f;
#pragma unroll
    for (int t = 0; t < 2; ++t) {
        float4 v = row[lane + 32 * t];
        s += v.x * v.x + v.y * v.y + v.z * v.z + v.w * v.w;
    }
#pragma unroll
    for (int o = 16; o; o >>= 1) s += __shfl_xor_sync(0xffffffffu, s, o);
    if (lane == 0) g_esq[k] = s;
}

// ---------------------------------------------------------------------------
// main: fp16 mma.sync, 64x64 tiles, 8 warps, 2 CTAs/SM, top-3 screening
// ---------------------------------------------------------------------------
__global__ __launch_bounds__(256, 2) void argmin_hmma(const float* __restrict__ x) {
    const uint32_t sb    = smem_u32(dynsmem);
    const uint32_t sb_xs = sb;
    const uint32_t sb_es = sb + XS_BYTES;

    const int tid = threadIdx.x;
    const int wid = tid >> 5, l = tid & 31;
    const int warp_m = wid >> 2, warp_n = wid & 3;   // 2 x 4 warps, 32x16 tiles
    const int row0 = blockIdx.x * BMM;
    const int q    = blockIdx.y;
    const int qcode0 = q * (KCB / NQ);

    // ---- prologue: x fp32 -> half into smem (64 rows); es chunks 0,1 ----
#pragma unroll
    for (int t = 0; t < 8; ++t) {
        int lin = t * 256 + tid;                      // 2048 = 64 rows x 32 segs
        int row = lin >> 5, seg = lin & 31;
        const float4* xr = (const float4*)(x + (size_t)(row0 + row) * DIM) + seg * 2;
        float4 v0 = xr[0], v1 = xr[1];
        __half2 h0 = __floats2half2_rn(v0.x, v0.y), h1 = __floats2half2_rn(v0.z, v0.w);
        __half2 h2 = __floats2half2_rn(v1.x, v1.y), h3 = __floats2half2_rn(v1.z, v1.w);
        uint4 pk = { *(uint32_t*)&h0, *(uint32_t*)&h1, *(uint32_t*)&h2, *(uint32_t*)&h3 };
        *(uint4*)(dynsmem + (row * XSTR + seg * 8) * 2) = pk;
    }
#pragma unroll
    for (int t = 0; t < 8; ++t) {                     // es chunk 0 (64 codes)
        int lin = t * 256 + tid;
        int row = lin >> 5, seg = lin & 31;
        cpa16(sb_es + (row * XSTR + seg * 8) * 2,
              g_eh + (size_t)(qcode0 + row) * DIM + seg * 8);
    }
    CP_COMMIT();
#pragma unroll
    for (int t = 0; t < 8; ++t) {                     // es chunk 1
        int lin = t * 256 + tid;
        int row = lin >> 5, seg = lin & 31;
        cpa16(sb_es + ES_BUF_BYTES + (row * XSTR + seg * 8) * 2,
              g_eh + (size_t)(qcode0 + BNN + row) * DIM + seg * 8);
    }
    CP_COMMIT();

    uint32_t a_base[2];
#pragma unroll
    for (int mi = 0; mi < 2; ++mi)
        a_base[mi] = sb_xs + ((warp_m * 32 + mi * 16 + (l & 15)) * XSTR + (l >> 4) * 8) * 2;
    const int bcode = (l & 7) + ((l >> 4) << 3);
    const int bkh   = (l >> 3) & 1;
    const uint32_t b_base = sb_es + ((warp_n * 16 + bcode) * XSTR + bkh * 8) * 2;

    float acc[2][2][4];
#pragma unroll
    for (int mi = 0; mi < 2; ++mi)
#pragma unroll
        for (int ni = 0; ni < 2; ++ni)
#pragma unroll
            for (int r = 0; r < 4; ++r) acc[mi][ni][r] = 0.f;

    float bv[4], sv[4], tv[4];
    int   bi[4], si[4];
#pragma unroll
    for (int r = 0; r < 4; ++r) {
        bv[r] = FLT_MAX; sv[r] = FLT_MAX; tv[r] = FLT_MAX; bi[r] = 0; si[r] = 0;
    }

    for (int c = 0; c < CPQ; ++c) {
        CP_WAIT1();
        __syncthreads();
        const uint32_t bofs = (c & 1) ? ES_BUF_BYTES : 0;

#pragma unroll 4
        for (int kk = 0; kk < 16; ++kk) {
            uint32_t a[2][4], b[4];
#pragma unroll
            for (int mi = 0; mi < 2; ++mi)
                ldmx4(a[mi][0], a[mi][1], a[mi][2], a[mi][3], a_base[mi] + kk * 32);
            ldmx4(b[0], b[1], b[2], b[3], b_base + bofs + kk * 32);
#pragma unroll
            for (int mi = 0; mi < 2; ++mi) {
#pragma unroll
                for (int ni = 0; ni < 2; ++ni) {
                    uint32_t bf[2] = { b[ni * 2], b[ni * 2 + 1] };
                    mma16816(acc[mi][ni], a[mi], bf);
                }
            }
        }
        __syncthreads();
        if (c + 2 < CPQ) {                            // prefetch chunk c+2
#pragma unroll
            for (int t = 0; t < 8; ++t) {
                int lin = t * 256 + tid;
                int row = lin >> 5, seg = lin & 31;
                cpa16(sb_es + bofs + (row * XSTR + seg * 8) * 2,
                      g_eh + (size_t)(qcode0 + (c + 2) * BNN + row) * DIM + seg * 8);
            }
        }
        CP_COMMIT();

        // ---- epilogue: distances + top-3 (16 cols per warp) ----
        const int colbase = qcode0 + c * BNN + warp_n * 16 + (l & 3) * 2;
#pragma unroll
        for (int ni = 0; ni < 2; ++ni) {
            float2 eq = __ldg((const float2*)(g_esq + colbase + ni * 8));
#pragma unroll
            for (int mi = 0; mi < 2; ++mi) {
#pragma unroll
                for (int h = 0; h < 2; ++h) {
                    int r = mi * 2 + h;
                    float d0 = eq.x - 2.0f * acc[mi][ni][h * 2];
                    float d1 = eq.y - 2.0f * acc[mi][ni][h * 2 + 1];
                    acc[mi][ni][h * 2] = 0.f; acc[mi][ni][h * 2 + 1] = 0.f;
                    int code = colbase + ni * 8;
                    ins3(d0, code,     bv[r], sv[r], tv[r], bi[r], si[r]);
                    ins3(d1, code + 1, bv[r], sv[r], tv[r], bi[r], si[r]);
                }
            }
        }
    }

    // ---- cross-thread top-3 merge (16 owners per row, 64 rows) ----
    float* rb = (float*)(dynsmem + XS_BYTES);         // overlay on es (loop done)
    float* rs = rb + 1024;
    float* rt = rs + 1024;
    int*   r1 = (int*)(rt + 1024);
    int*   r2 = r1 + 1024;
    __syncthreads();
#pragma unroll
    for (int mi = 0; mi < 2; ++mi)
#pragma unroll
        for (int h = 0; h < 2; ++h) {
            int row  = warp_m * 32 + mi * 16 + (l >> 2) + 8 * h;
            int slot = warp_n * 4 + (l & 3);
            int r = mi * 2 + h;
            rb[row * 16 + slot] = bv[r];
            rs[row * 16 + slot] = sv[r];
            rt[row * 16 + slot] = tv[r];
            r1[row * 16 + slot] = bi[r];
            r2[row * 16 + slot] = si[r];
        }
    __syncthreads();
    if (tid < BMM) {
        float b1 = FLT_MAX, s1 = FLT_MAX, t1 = FLT_MAX;
        int i1 = 0, i2 = 0;
#pragma unroll
        for (int t = 0; t < 16; ++t) {
            ins3(rb[tid * 16 + t], r1[tid * 16 + t], b1, s1, t1, i1, i2);
            ins3(rs[tid * 16 + t], r2[tid * 16 + t], b1, s1, t1, i1, i2);
            float t2 = rt[tid * 16 + t];
            if (t2 < t1) t1 = t2;
        }
        int grow = row0 + tid;
        g_pb[q * NTOT + grow] = b1;
        g_ps[q * NTOT + grow] = s1;
        g_pt[q * NTOT + grow] = t1;
        g_pi1[q * NTOT + grow] = i1;
        g_pi2[q * NTOT + grow] = i2;
    }
}

// ---------------------------------------------------------------------------
// merge quarters: global top-3; route to direct / pairwise / full rescue
// ---------------------------------------------------------------------------
__global__ void merge_kernel() {
    int n = blockIdx.x * blockDim.x + threadIdx.x;
    if (n >= NTOT) return;
    float b1 = FLT_MAX, s1 = FLT_MAX, t1 = FLT_MAX;
    int i1 = 0, i2 = 0;
#pragma unroll
    for (int q = 0; q < NQ; ++q) {
        ins3(g_pb[q * NTOT + n], g_pi1[q * NTOT + n], b1, s1, t1, i1, i2);
        ins3(g_ps[q * NTOT + n], g_pi2[q * NTOT + n], b1, s1, t1, i1, i2);
        float t2 = g_pt[q * NTOT + n];
        if (t2 < t1) t1 = t2;
    }
    if (t1 - b1 < MARGIN) {
        int s = atomicAdd(&g_nflag, 1);
        g_flag[s] = n;
        g_bestkey[n] = 0xFFFFFFFFFFFFFFFFull;
    } else if (s1 - b1 < MARGIN) {
        int s = atomicAdd(&g_npair, 1);
        g_pairn[s] = n;
        g_pairc[s] = make_int2(i1, i2);
    } else {
        g_best[n] = i1;
    }
}

// ---------------------------------------------------------------------------
// pairwise exact: one warp per flagged pair, two fp32 dots
// ---------------------------------------------------------------------------
__global__ __launch_bounds__(256, 1)
void pair_kernel(const float* __restrict__ x, const float* __restrict__ embed) {
    int e = blockIdx.x * 8 + (threadIdx.x >> 5);
    if (e >= g_npair) return;
    int lane = threadIdx.x & 31;
    int n = g_pairn[e];
    int2 c = g_pairc[e];

    const float4* xr = (const float4*)(x + (size_t)n * DIM) + lane * 2;
    const float4* e1 = (const float4*)(embed + (size_t)c.x * DIM) + lane * 2;
    const float4* e2 = (const float4*)(embed + (size_t)c.y * DIM) + lane * 2;
    float dot1 = 0.f, dot2 = 0.f;
#pragma unroll
    for (int t = 0; t < 2; ++t) {
        float4 xv = xr[t], a = e1[t], b = e2[t];
        dot1 += xv.x * a.x + xv.y * a.y + xv.z * a.z + xv.w * a.w;
        dot2 += xv.x * b.x + xv.y * b.y + xv.z * b.z + xv.w * b.w;
    }
#pragma unroll
    for (int o = 16; o; o >>= 1) {
        dot1 += __shfl_xor_sync(0xffffffffu, dot1, o);
        dot2 += __shfl_xor_sync(0xffffffffu, dot2, o);
    }
    if (lane == 0) {
        float d1 = g_esq[c.x] - 2.0f * dot1;
        float d2 = g_esq[c.y] - 2.0f * dot2;
        int win = (d1 < d2) ? c.x : (d2 < d1) ? c.y : min(c.x, c.y);
        g_best[n] = win;
    }
}

// ---------------------------------------------------------------------------
// full rescue: exact fp32 rescore of flagged rows over 64 code chunks
// ---------------------------------------------------------------------------
#define ESL 33
#define RESCUE_SMEM ((BM*DIM + BN*ESL + BN + BM*16) * 4 + (BM*16) * 4 + BM * 4)

__global__ __launch_bounds__(256, 1)
void rescue_kernel(const float* __restrict__ x, const float* __restrict__ embed) {
    const int nf = g_nflag;
    const int base = blockIdx.x * BM;
    if (base >= nf) return;
    const int code0 = blockIdx.y * BN;

    float* xs      = (float*)dynsmem;
    float* es      = xs + BM * DIM;
    float* esq_s   = es + BN * ESL;
    float* red_val = esq_s + BN;
    int*   red_idx = (int*)(red_val + BM * 16);
    int*   rows_l  = red_idx + BM * 16;

    const int tid = threadIdx.x;
    const int ty = tid >> 4, tx = tid & 15;

    if (tid < BM) {
        int s = base + tid;
        rows_l[tid] = g_flag[(s < nf) ? s : base];
    }
    if (tid < BN) esq_s[tid] = g_esq[code0 + tid];
    __syncthreads();

#pragma unroll 4
    for (int i = 0; i < 32; ++i) {
        int lin = i * 256 + tid;
        int row = lin >> 6, qd = lin & 63;
        ((float4*)(xs + row * DIM))[qd] =
            ((const float4*)(x + (size_t)rows_l[row] * DIM))[qd];
    }

    float best_val[8]; int best_idx[8];
#pragma unroll
    for (int i = 0; i < 8; ++i) { best_val[i] = FLT_MAX; best_idx[i] = 0; }

    float acc[8][8];
#pragma unroll
    for (int i = 0; i < 8; ++i)
#pragma unroll
        for (int j = 0; j < 8; ++j) acc[i][j] = 0.f;

    for (int cb = 0; cb < DIM / 32; ++cb) {
        __syncthreads();
#pragma unroll
        for (int lgl = 0; lgl < 4; ++lgl) {
            int lin = tid + lgl * 256;
            int col = lin >> 3, qd = lin & 7;
            float4 v = *(const float4*)(embed + (size_t)(code0 + col) * DIM + cb * 32 + qd * 4);
            es[col * ESL + qd * 4 + 0] = v.x;
            es[col * ESL + qd * 4 + 1] = v.y;
            es[col * ESL + qd * 4 + 2] = v.z;
            es[col * ESL + qd * 4 + 3] = v.w;
        }
        __syncthreads();
        const float* xbase = xs + cb * 32;
#pragma unroll
        for (int kk = 0; kk < 32; ++kk) {
            float xr[8], er[8];
#pragma unroll
            for (int i = 0; i < 8; ++i) xr[i] = xbase[(ty + 16 * i) * DIM + kk];
#pragma unroll
            for (int j = 0; j < 8; ++j) er[j] = es[(tx + 16 * j) * ESL + kk];
#pragma unroll
            for (int i = 0; i < 8; ++i)
#pragma unroll
                for (int j = 0; j < 8; ++j)
                    acc[i][j] = fmaf(xr[i], er[j], acc[i][j]);
        }
    }
#pragma unroll
    for (int j = 0; j < 8; ++j) {
        int code = code0 + tx + 16 * j;
        float esq = esq_s[tx + 16 * j];
#pragma unroll
        for (int i = 0; i < 8; ++i) {
            float d = esq - 2.0f * acc[i][j];
            if (d < best_val[i] || (d == best_val[i] && code < best_idx[i])) {
                best_val[i] = d; best_idx[i] = code;
            }
        }
    }

    __syncthreads();
#pragma unroll
    for (int i = 0; i < 8; ++i) {
        int r = ty + 16 * i;
        red_val[r * 16 + tx] = best_val[i];
        red_idx[r * 16 + tx] = best_idx[i];
    }
    __syncthreads();
    if (tid < BM) {
        float bvv = red_val[tid * 16];
        int   bii = red_idx[tid * 16];
#pragma unroll
        for (int t = 1; t < 16; ++t) {
            float v = red_val[tid * 16 + t];
            int  ix = red_idx[tid * 16 + t];
            if (v < bvv || (v == bvv && ix < bii)) { bvv = v; bii = ix; }
        }
        atomicMin(&g_bestkey[rows_l[tid]], mkkey(bvv, bii));
    }
}

__global__ void finalize_kernel() {
    int s = blockIdx.x * blockDim.x + threadIdx.x;
    if (s < g_nflag) {
        int row = g_flag[s];
        g_best[row] = (int)(g_bestkey[row] & 0xffffffffu);
    }
}

// gather: 4 rows per 256-thread block
__global__ void gather_kernel(const float* __restrict__ embed, float* __restrict__ out) {
    int row = blockIdx.x * 4 + (threadIdx.x >> 6);
    int t   = threadIdx.x & 63;
    int idx = g_best[row];
    const float4* src = (const float4*)(embed + (size_t)idx * DIM);
    float4*       dst = (float4*)(out + (size_t)row * DIM);
    dst[t] = src[t];
}

// ---------------------------------------------------------------------------
extern "C" void kernel_launch(void* const* d_in, const int* in_sizes, int n_in,
                              void* d_out, int out_size) {
    const float* x     = (const float*)d_in[0];
    const float* embed = (const float*)d_in[1];
    float*       out   = (float*)d_out;

    cudaFuncSetAttribute(argmin_hmma, cudaFuncAttributeMaxDynamicSharedMemorySize, MAIN_SMEM);
    cudaFuncSetAttribute(rescue_kernel, cudaFuncAttributeMaxDynamicSharedMemorySize, RESCUE_SMEM);

    split_kernel<<<1024, 256>>>(embed);
    esq_kernel<<<KCB, 32>>>(embed);
    argmin_hmma<<<dim3(NTOT / BMM, NQ), 256, MAIN_SMEM>>>(x);
    merge_kernel<<<NTOT / 256, 256>>>();
    pair_kernel<<<NTOT / 8, 256>>>(x, embed);
    rescue_kernel<<<dim3(NTOT / BM, KCB / BN), 256, RESCUE_SMEM>>>(x, embed);
    finalize_kernel<<<NTOT / 256, 256>>>();
    gather_kernel<<<NTOT / 4, 256>>>(embed, out);
}

// round 14
// speedup vs baseline: 1.5117x; 1.5117x over previous
#include <cuda_runtime.h>
#include <cuda_fp16.h>
#include <cfloat>
#include <cstdint>

#define DIM   256
#define KCB   8192
#define NTOT  32768
#define BM    128
#define BN    128
#define NQ    4
#define CPQ   16
#define MARGIN 0.25f

#define XSTR  264
#define ES_BUF_BYTES (128 * XSTR * 2)
#define MAIN_SMEM (3 * 128 * XSTR * 2)

// ---------------- device scratch ----------------
__device__ __align__(16) __half g_eh[KCB * DIM];
__device__ float g_esq[KCB];
__device__ int   g_best[NTOT];
__device__ int   g_flag[NTOT];
__device__ unsigned long long g_bestkey[NTOT];
__device__ int   g_nflag;
__device__ int   g_npair;
__device__ int   g_pairn[NTOT];
__device__ int2  g_pairc[NTOT];
__device__ float g_pb[NQ * NTOT];
__device__ float g_ps[NQ * NTOT];
__device__ float g_pt[NQ * NTOT];
__device__ int   g_pi1[NQ * NTOT];
__device__ int   g_pi2[NQ * NTOT];

extern __shared__ char dynsmem[];

__device__ __forceinline__ uint32_t smem_u32(const void* p) {
    uint32_t a;
    asm("{ .reg .u64 t; cvta.to.shared.u64 t, %1; cvt.u32.u64 %0, t; }" : "=r"(a) : "l"(p));
    return a;
}
__device__ __forceinline__ void cpa16(uint32_t dst, const void* src) {
    asm volatile("cp.async.cg.shared.global [%0], [%1], 16;" :: "r"(dst), "l"(src));
}
#define CP_COMMIT() asm volatile("cp.async.commit_group;" ::: "memory")
#define CP_WAIT1()  asm volatile("cp.async.wait_group 1;" ::: "memory")

__device__ __forceinline__ void ldmx4(uint32_t& r0, uint32_t& r1, uint32_t& r2, uint32_t& r3,
                                      uint32_t addr) {
    asm volatile("ldmatrix.sync.aligned.m8n8.x4.shared.b16 {%0,%1,%2,%3}, [%4];"
                 : "=r"(r0), "=r"(r1), "=r"(r2), "=r"(r3) : "r"(addr));
}
__device__ __forceinline__ void mma16816(float* c, const uint32_t* a, const uint32_t* b) {
    asm volatile("mma.sync.aligned.m16n8k16.row.col.f32.f16.f16.f32 "
                 "{%0,%1,%2,%3}, {%4,%5,%6,%7}, {%8,%9}, {%0,%1,%2,%3};"
                 : "+f"(c[0]), "+f"(c[1]), "+f"(c[2]), "+f"(c[3])
                 : "r"(a[0]), "r"(a[1]), "r"(a[2]), "r"(a[3]), "r"(b[0]), "r"(b[1]));
}
__device__ __forceinline__ unsigned long long mkkey(float f, int idx) {
    unsigned u = __float_as_uint(f);
    u = (u & 0x80000000u) ? ~u : (u | 0x80000000u);
    return ((unsigned long long)u << 32) | (unsigned)idx;
}
__device__ __forceinline__ void ins3(float v, int ix,
                                     float& b, float& s, float& t, int& ib, int& is_) {
    if (v < b)      { t = s; s = b; is_ = ib; b = v; ib = ix; }
    else if (v < s) { t = s; s = v; is_ = ix; }
    else if (v < t) { t = v; }
}

// ---------------------------------------------------------------------------
// fused: embed fp32 -> fp16 conversion + |e|^2, one warp per code row
// ---------------------------------------------------------------------------
__global__ void prep_kernel(const float* __restrict__ embed) {
    if (blockIdx.x == 0 && threadIdx.x == 0) { g_nflag = 0; g_npair = 0; }
    int k = blockIdx.x * 8 + (threadIdx.x >> 5);
    if (k >= KCB) return;
    int lane = threadIdx.x & 31;
    const float4* row = (const float4*)(embed + (size_t)k * DIM);
    __half2* dst = (__half2*)(g_eh + (size_t)k * DIM);
    float s = 0.f;
#pragma unroll
    for (int t = 0; t < 2; ++t) {
        float4 v = row[lane + 32 * t];
        s += v.x * v.x + v.y * v.y + v.z * v.z + v.w * v.w;
        dst[(lane + 32 * t) * 2]     = __floats2half2_rn(v.x, v.y);
        dst[(lane + 32 * t) * 2 + 1] = __floats2half2_rn(v.z, v.w);
    }
#pragma unroll
    for (int o = 16; o; o >>= 1) s += __shfl_xor_sync(0xffffffffu, s, o);
    if (lane == 0) g_esq[k] = s;
}

// ---------------------------------------------------------------------------
// main: fp16 mma.sync (f32 accum), grid (rowblk, quarter), top-3 screening
// ---------------------------------------------------------------------------
__global__ __launch_bounds__(512, 1) void argmin_hmma(const float* __restrict__ x) {
    const uint32_t sb    = smem_u32(dynsmem);
    const uint32_t sb_xs = sb;
    const uint32_t sb_es = sb + 128 * XSTR * 2;

    const int tid = threadIdx.x;
    const int wid = tid >> 5, l = tid & 31;
    const int warp_m = wid >> 2, warp_n = wid & 3;
    const int row0 = blockIdx.x * BM;
    const int q    = blockIdx.y;
    const int qcode0 = q * (KCB / NQ);

    // ---- prologue: x fp32 -> half into smem; es chunks 0,1 via cp.async ----
#pragma unroll
    for (int t = 0; t < 8; ++t) {
        int lin = t * 512 + tid;
        int row = lin >> 5, seg = lin & 31;
        const float4* xr = (const float4*)(x + (size_t)(row0 + row) * DIM) + seg * 2;
        float4 v0 = xr[0], v1 = xr[1];
        __half2 h0 = __floats2half2_rn(v0.x, v0.y), h1 = __floats2half2_rn(v0.z, v0.w);
        __half2 h2 = __floats2half2_rn(v1.x, v1.y), h3 = __floats2half2_rn(v1.z, v1.w);
        uint4 pk = { *(uint32_t*)&h0, *(uint32_t*)&h1, *(uint32_t*)&h2, *(uint32_t*)&h3 };
        *(uint4*)(dynsmem + (row * XSTR + seg * 8) * 2) = pk;
    }
#pragma unroll
    for (int t = 0; t < 8; ++t) {
        int lin = t * 512 + tid;
        int row = lin >> 5, seg = lin & 31;
        cpa16(sb_es + (row * XSTR + seg * 8) * 2,
              g_eh + (size_t)(qcode0 + row) * DIM + seg * 8);
    }
    CP_COMMIT();
#pragma unroll
    for (int t = 0; t < 8; ++t) {
        int lin = t * 512 + tid;
        int row = lin >> 5, seg = lin & 31;
        cpa16(sb_es + ES_BUF_BYTES + (row * XSTR + seg * 8) * 2,
              g_eh + (size_t)(qcode0 + 128 + row) * DIM + seg * 8);
    }
    CP_COMMIT();

    uint32_t a_base[2];
#pragma unroll
    for (int mi = 0; mi < 2; ++mi)
        a_base[mi] = sb_xs + ((warp_m * 32 + mi * 16 + (l & 15)) * XSTR + (l >> 4) * 8) * 2;
    const int bcode = (l & 7) + ((l >> 4) << 3);
    const int bkh   = (l >> 3) & 1;
    uint32_t b_base[2];
#pragma unroll
    for (int bt = 0; bt < 2; ++bt)
        b_base[bt] = sb_es + ((warp_n * 32 + bt * 16 + bcode) * XSTR + bkh * 8) * 2;

    float acc[2][4][4];
#pragma unroll
    for (int mi = 0; mi < 2; ++mi)
#pragma unroll
        for (int ni = 0; ni < 4; ++ni)
#pragma unroll
            for (int r = 0; r < 4; ++r) acc[mi][ni][r] = 0.f;

    float bv[4], sv[4], tv[4];
    int   bi[4], si[4];
#pragma unroll
    for (int r = 0; r < 4; ++r) {
        bv[r] = FLT_MAX; sv[r] = FLT_MAX; tv[r] = FLT_MAX; bi[r] = 0; si[r] = 0;
    }

    for (int c = 0; c < CPQ; ++c) {
        CP_WAIT1();
        __syncthreads();
        const uint32_t bofs = (c & 1) ? ES_BUF_BYTES : 0;

#pragma unroll 4
        for (int kk = 0; kk < 16; ++kk) {
            uint32_t a[2][4], b[2][4];
#pragma unroll
            for (int mi = 0; mi < 2; ++mi)
                ldmx4(a[mi][0], a[mi][1], a[mi][2], a[mi][3], a_base[mi] + kk * 32);
#pragma unroll
            for (int bt = 0; bt < 2; ++bt)
                ldmx4(b[bt][0], b[bt][1], b[bt][2], b[bt][3], b_base[bt] + bofs + kk * 32);
#pragma unroll
            for (int mi = 0; mi < 2; ++mi) {
#pragma unroll
                for (int ni = 0; ni < 4; ++ni) {
                    uint32_t bf[2] = { b[ni >> 1][(ni & 1) * 2], b[ni >> 1][(ni & 1) * 2 + 1] };
                    mma16816(acc[mi][ni], a[mi], bf);
                }
            }
        }
        __syncthreads();
        if (c + 2 < CPQ) {
#pragma unroll
            for (int t = 0; t < 8; ++t) {
                int lin = t * 512 + tid;
                int row = lin >> 5, seg = lin & 31;
                cpa16(sb_es + bofs + (row * XSTR + seg * 8) * 2,
                      g_eh + (size_t)(qcode0 + (c + 2) * 128 + row) * DIM + seg * 8);
            }
        }
        CP_COMMIT();

        // ---- epilogue: distances + top-3 ----
        const int colbase = qcode0 + c * 128 + warp_n * 32 + (l & 3) * 2;
#pragma unroll
        for (int ni = 0; ni < 4; ++ni) {
            float2 eq = __ldg((const float2*)(g_esq + colbase + ni * 8));
#pragma unroll
            for (int mi = 0; mi < 2; ++mi) {
#pragma unroll
                for (int h = 0; h < 2; ++h) {
                    int r = mi * 2 + h;
                    float d0 = eq.x - 2.0f * acc[mi][ni][h * 2];
                    float d1 = eq.y - 2.0f * acc[mi][ni][h * 2 + 1];
                    acc[mi][ni][h * 2] = 0.f; acc[mi][ni][h * 2 + 1] = 0.f;
                    int code = colbase + ni * 8;
                    ins3(d0, code,     bv[r], sv[r], tv[r], bi[r], si[r]);
                    ins3(d1, code + 1, bv[r], sv[r], tv[r], bi[r], si[r]);
                }
            }
        }
    }

    // ---- cross-thread top-3 merge (16 owners per row) ----
    float* rb = (float*)(dynsmem + 128 * XSTR * 2);
    float* rs = rb + 2048;
    float* rt = rs + 2048;
    int*   r1 = (int*)(rt + 2048);
    int*   r2 = r1 + 2048;
    __syncthreads();
#pragma unroll
    for (int mi = 0; mi < 2; ++mi)
#pragma unroll
        for (int h = 0; h < 2; ++h) {
            int row  = warp_m * 32 + mi * 16 + (l >> 2) + 8 * h;
            int slot = warp_n * 4 + (l & 3);
            int r = mi * 2 + h;
            rb[row * 16 + slot] = bv[r];
            rs[row * 16 + slot] = sv[r];
            rt[row * 16 + slot] = tv[r];
            r1[row * 16 + slot] = bi[r];
            r2[row * 16 + slot] = si[r];
        }
    __syncthreads();
    if (tid < 128) {
        float b1 = FLT_MAX, s1 = FLT_MAX, t1 = FLT_MAX;
        int i1 = 0, i2 = 0;
#pragma unroll
        for (int t = 0; t < 16; ++t) {
            ins3(rb[tid * 16 + t], r1[tid * 16 + t], b1, s1, t1, i1, i2);
            ins3(rs[tid * 16 + t], r2[tid * 16 + t], b1, s1, t1, i1, i2);
            float t2 = rt[tid * 16 + t];
            if (t2 < t1) t1 = t2;
        }
        int grow = row0 + tid;
        g_pb[q * NTOT + grow] = b1;
        g_ps[q * NTOT + grow] = s1;
        g_pt[q * NTOT + grow] = t1;
        g_pi1[q * NTOT + grow] = i1;
        g_pi2[q * NTOT + grow] = i2;
    }
}

// ---------------------------------------------------------------------------
// merge quarters: global top-3; route to direct / pairwise / full rescue
// ---------------------------------------------------------------------------
__global__ void merge_kernel() {
    int n = blockIdx.x * blockDim.x + threadIdx.x;
    if (n >= NTOT) return;
    float b1 = FLT_MAX, s1 = FLT_MAX, t1 = FLT_MAX;
    int i1 = 0, i2 = 0;
#pragma unroll
    for (int q = 0; q < NQ; ++q) {
        ins3(g_pb[q * NTOT + n], g_pi1[q * NTOT + n], b1, s1, t1, i1, i2);
        ins3(g_ps[q * NTOT + n], g_pi2[q * NTOT + n], b1, s1, t1, i1, i2);
        float t2 = g_pt[q * NTOT + n];
        if (t2 < t1) t1 = t2;
    }
    if (t1 - b1 < MARGIN) {
        int s = atomicAdd(&g_nflag, 1);
        g_flag[s] = n;
        g_bestkey[n] = 0xFFFFFFFFFFFFFFFFull;
    } else if (s1 - b1 < MARGIN) {
        int s = atomicAdd(&g_npair, 1);
        g_pairn[s] = n;
        g_pairc[s] = make_int2(i1, i2);
    } else {
        g_best[n] = i1;
    }
}

// ---------------------------------------------------------------------------
// pairwise exact: one warp per flagged pair, grid-stride over entries
// ---------------------------------------------------------------------------
__global__ __launch_bounds__(256, 1)
void pair_kernel(const float* __restrict__ x, const float* __restrict__ embed) {
    const int np = g_npair;
    int lane = threadIdx.x & 31;
    for (int e = blockIdx.x * 8 + (threadIdx.x >> 5); e < np; e += gridDim.x * 8) {
        int n = g_pairn[e];
        int2 c = g_pairc[e];
        const float4* xr = (const float4*)(x + (size_t)n * DIM) + lane * 2;
        const float4* e1 = (const float4*)(embed + (size_t)c.x * DIM) + lane * 2;
        const float4* e2 = (const float4*)(embed + (size_t)c.y * DIM) + lane * 2;
        float dot1 = 0.f, dot2 = 0.f;
#pragma unroll
        for (int t = 0; t < 2; ++t) {
            float4 xv = xr[t], a = e1[t], b = e2[t];
            dot1 += xv.x * a.x + xv.y * a.y + xv.z * a.z + xv.w * a.w;
            dot2 += xv.x * b.x + xv.y * b.y + xv.z * b.z + xv.w * b.w;
        }
#pragma unroll
        for (int o = 16; o; o >>= 1) {
            dot1 += __shfl_xor_sync(0xffffffffu, dot1, o);
            dot2 += __shfl_xor_sync(0xffffffffu, dot2, o);
        }
        if (lane == 0) {
            float d1 = g_esq[c.x] - 2.0f * dot1;
            float d2 = g_esq[c.y] - 2.0f * dot2;
            int win = (d1 < d2) ? c.x : (d2 < d1) ? c.y : min(c.x, c.y);
            g_best[n] = win;
        }
    }
}

// ---------------------------------------------------------------------------
// full rescue: exact fp32 rescore of flagged rows over 64 code chunks
// ---------------------------------------------------------------------------
#define ESL 33
#define RESCUE_SMEM ((BM*DIM + BN*ESL + BN + BM*16) * 4 + (BM*16) * 4 + BM * 4)

__global__ __launch_bounds__(256, 1)
void rescue_kernel(const float* __restrict__ x, const float* __restrict__ embed) {
    const int nf = g_nflag;
    const int base = blockIdx.x * BM;
    if (base >= nf) return;
    const int code0 = blockIdx.y * BN;

    float* xs      = (float*)dynsmem;
    float* es      = xs + BM * DIM;
    float* esq_s   = es + BN * ESL;
    float* red_val = esq_s + BN;
    int*   red_idx = (int*)(red_val + BM * 16);
    int*   rows_l  = red_idx + BM * 16;

    const int tid = threadIdx.x;
    const int ty = tid >> 4, tx = tid & 15;

    if (tid < BM) {
        int s = base + tid;
        rows_l[tid] = g_flag[(s < nf) ? s : base];
    }
    if (tid < BN) esq_s[tid] = g_esq[code0 + tid];
    __syncthreads();

#pragma unroll 4
    for (int i = 0; i < 32; ++i) {
        int lin = i * 256 + tid;
        int row = lin >> 6, qd = lin & 63;
        ((float4*)(xs + row * DIM))[qd] =
            ((const float4*)(x + (size_t)rows_l[row] * DIM))[qd];
    }

    float best_val[8]; int best_idx[8];
#pragma unroll
    for (int i = 0; i < 8; ++i) { best_val[i] = FLT_MAX; best_idx[i] = 0; }

    float acc[8][8];
#pragma unroll
    for (int i = 0; i < 8; ++i)
#pragma unroll
        for (int j = 0; j < 8; ++j) acc[i][j] = 0.f;

    for (int cb = 0; cb < DIM / 32; ++cb) {
        __syncthreads();
#pragma unroll
        for (int lgl = 0; lgl < 4; ++lgl) {
            int lin = tid + lgl * 256;
            int col = lin >> 3, qd = lin & 7;
            float4 v = *(const float4*)(embed + (size_t)(code0 + col) * DIM + cb * 32 + qd * 4);
            es[col * ESL + qd * 4 + 0] = v.x;
            es[col * ESL + qd * 4 + 1] = v.y;
            es[col * ESL + qd * 4 + 2] = v.z;
            es[col * ESL + qd * 4 + 3] = v.w;
        }
        __syncthreads();
        const float* xbase = xs + cb * 32;
#pragma unroll
        for (int kk = 0; kk < 32; ++kk) {
            float xr[8], er[8];
#pragma unroll
            for (int i = 0; i < 8; ++i) xr[i] = xbase[(ty + 16 * i) * DIM + kk];
#pragma unroll
            for (int j = 0; j < 8; ++j) er[j] = es[(tx + 16 * j) * ESL + kk];
#pragma unroll
            for (int i = 0; i < 8; ++i)
#pragma unroll
                for (int j = 0; j < 8; ++j)
                    acc[i][j] = fmaf(xr[i], er[j], acc[i][j]);
        }
    }
#pragma unroll
    for (int j = 0; j < 8; ++j) {
        int code = code0 + tx + 16 * j;
        float esq = esq_s[tx + 16 * j];
#pragma unroll
        for (int i = 0; i < 8; ++i) {
            float d = esq - 2.0f * acc[i][j];
            if (d < best_val[i] || (d == best_val[i] && code < best_idx[i])) {
                best_val[i] = d; best_idx[i] = code;
            }
        }
    }

    __syncthreads();
#pragma unroll
    for (int i = 0; i < 8; ++i) {
        int r = ty + 16 * i;
        red_val[r * 16 + tx] = best_val[i];
        red_idx[r * 16 + tx] = best_idx[i];
    }
    __syncthreads();
    if (tid < BM) {
        float bvv = red_val[tid * 16];
        int   bii = red_idx[tid * 16];
#pragma unroll
        for (int t = 1; t < 16; ++t) {
            float v = red_val[tid * 16 + t];
            int  ix = red_idx[tid * 16 + t];
            if (v < bvv || (v == bvv && ix < bii)) { bvv = v; bii = ix; }
        }
        atomicMin(&g_bestkey[rows_l[tid]], mkkey(bvv, bii));
    }
}

__global__ void finalize_kernel() {
    int s = blockIdx.x * blockDim.x + threadIdx.x;
    if (s < g_nflag) {
        int row = g_flag[s];
        g_best[row] = (int)(g_bestkey[row] & 0xffffffffu);
    }
}

// gather: 4 rows per 256-thread block
__global__ void gather_kernel(const float* __restrict__ embed, float* __restrict__ out) {
    int row = blockIdx.x * 4 + (threadIdx.x >> 6);
    int t   = threadIdx.x & 63;
    int idx = g_best[row];
    const float4* src = (const float4*)(embed + (size_t)idx * DIM);
    float4*       dst = (float4*)(out + (size_t)row * DIM);
    dst[t] = src[t];
}

// ---------------------------------------------------------------------------
extern "C" void kernel_launch(void* const* d_in, const int* in_sizes, int n_in,
                              void* d_out, int out_size) {
    const float* x     = (const float*)d_in[0];
    const float* embed = (const float*)d_in[1];
    float*       out   = (float*)d_out;

    cudaFuncSetAttribute(argmin_hmma, cudaFuncAttributeMaxDynamicSharedMemorySize, MAIN_SMEM);
    cudaFuncSetAttribute(rescue_kernel, cudaFuncAttributeMaxDynamicSharedMemorySize, RESCUE_SMEM);

    prep_kernel<<<KCB / 8, 256>>>(embed);
    argmin_hmma<<<dim3(NTOT / BM, NQ), 512, MAIN_SMEM>>>(x);
    merge_kernel<<<NTOT / 256, 256>>>();
    pair_kernel<<<1024, 256>>>(x, embed);
    rescue_kernel<<<dim3(NTOT / BM, KCB / BN), 256, RESCUE_SMEM>>>(x, embed);
    finalize_kernel<<<NTOT / 256, 256>>>();
    gather_kernel<<<NTOT / 4, 256>>>(embed, out);
}

// round 15
// speedup vs baseline: 1.6203x; 1.0719x over previous
#include <cuda_runtime.h>
#include <cuda_fp16.h>
#include <cfloat>
#include <cstdint>

#define DIM   256
#define KCB   8192
#define NTOT  32768
#define BM    128
#define BN    128
#define NQ    4
#define CPQ   16
#define MARGIN 0.25f

#define XSTR  264
#define ES_BUF_BYTES (128 * XSTR * 2)
#define MAIN_SMEM (3 * 128 * XSTR * 2)

// ---------------- device scratch ----------------
__device__ __align__(16) __half g_eh[KCB * DIM];
__device__ float g_esq[KCB];
__device__ int   g_best[NTOT];
__device__ int   g_flag[NTOT];
__device__ unsigned long long g_bestkey[NTOT];
__device__ int   g_nflag;
__device__ int   g_npair;
__device__ int   g_pairn[NTOT];
__device__ int2  g_pairc[NTOT];
__device__ float g_pb[NQ * NTOT];
__device__ float g_ps[NQ * NTOT];
__device__ float g_pt[NQ * NTOT];
__device__ int   g_pi1[NQ * NTOT];
__device__ int   g_pi2[NQ * NTOT];

extern __shared__ char dynsmem[];

__device__ __forceinline__ uint32_t smem_u32(const void* p) {
    uint32_t a;
    asm("{ .reg .u64 t; cvta.to.shared.u64 t, %1; cvt.u32.u64 %0, t; }" : "=r"(a) : "l"(p));
    return a;
}
__device__ __forceinline__ void cpa16(uint32_t dst, const void* src) {
    asm volatile("cp.async.cg.shared.global [%0], [%1], 16;" :: "r"(dst), "l"(src));
}
#define CP_COMMIT() asm volatile("cp.async.commit_group;" ::: "memory")
#define CP_WAIT1()  asm volatile("cp.async.wait_group 1;" ::: "memory")

__device__ __forceinline__ void ldmx4(uint32_t& r0, uint32_t& r1, uint32_t& r2, uint32_t& r3,
                                      uint32_t addr) {
    asm volatile("ldmatrix.sync.aligned.m8n8.x4.shared.b16 {%0,%1,%2,%3}, [%4];"
                 : "=r"(r0), "=r"(r1), "=r"(r2), "=r"(r3) : "r"(addr));
}
__device__ __forceinline__ void mma16816(float* c, const uint32_t* a, const uint32_t* b) {
    asm volatile("mma.sync.aligned.m16n8k16.row.col.f32.f16.f16.f32 "
                 "{%0,%1,%2,%3}, {%4,%5,%6,%7}, {%8,%9}, {%0,%1,%2,%3};"
                 : "+f"(c[0]), "+f"(c[1]), "+f"(c[2]), "+f"(c[3])
                 : "r"(a[0]), "r"(a[1]), "r"(a[2]), "r"(a[3]), "r"(b[0]), "r"(b[1]));
}
__device__ __forceinline__ unsigned long long mkkey(float f, int idx) {
    unsigned u = __float_as_uint(f);
    u = (u & 0x80000000u) ? ~u : (u | 0x80000000u);
    return ((unsigned long long)u << 32) | (unsigned)idx;
}
__device__ __forceinline__ void ins3(float v, int ix,
                                     float& b, float& s, float& t, int& ib, int& is_) {
    if (v < b)      { t = s; s = b; is_ = ib; b = v; ib = ix; }
    else if (v < s) { t = s; s = v; is_ = ix; }
    else if (v < t) { t = v; }
}

// ---------------------------------------------------------------------------
// fused: embed fp32 -> fp16 conversion + |e|^2, one warp per code row
// ---------------------------------------------------------------------------
__global__ void prep_kernel(const float* __restrict__ embed) {
    if (blockIdx.x == 0 && threadIdx.x == 0) { g_nflag = 0; g_npair = 0; }
    int k = blockIdx.x * 8 + (threadIdx.x >> 5);
    if (k >= KCB) return;
    int lane = threadIdx.x & 31;
    const float4* row = (const float4*)(embed + (size_t)k * DIM);
    __half2* dst = (__half2*)(g_eh + (size_t)k * DIM);
    float s = 0.f;
#pragma unroll
    for (int t = 0; t < 2; ++t) {
        float4 v = row[lane + 32 * t];
        s += v.x * v.x + v.y * v.y + v.z * v.z + v.w * v.w;
        dst[(lane + 32 * t) * 2]     = __floats2half2_rn(v.x, v.y);
        dst[(lane + 32 * t) * 2 + 1] = __floats2half2_rn(v.z, v.w);
    }
#pragma unroll
    for (int o = 16; o; o >>= 1) s += __shfl_xor_sync(0xffffffffu, s, o);
    if (lane == 0) g_esq[k] = s;
}

// ---------------------------------------------------------------------------
// main: fp16 mma.sync (f32 accum), grid (rowblk, quarter), top-3 screening
// ---------------------------------------------------------------------------
__global__ __launch_bounds__(512, 1) void argmin_hmma(const float* __restrict__ x) {
    const uint32_t sb    = smem_u32(dynsmem);
    const uint32_t sb_xs = sb;
    const uint32_t sb_es = sb + 128 * XSTR * 2;

    const int tid = threadIdx.x;
    const int wid = tid >> 5, l = tid & 31;
    const int warp_m = wid >> 2, warp_n = wid & 3;
    const int row0 = blockIdx.x * BM;
    const int q    = blockIdx.y;
    const int qcode0 = q * (KCB / NQ);

    // ---- prologue: x fp32 -> half into smem; es chunks 0,1 via cp.async ----
#pragma unroll
    for (int t = 0; t < 8; ++t) {
        int lin = t * 512 + tid;
        int row = lin >> 5, seg = lin & 31;
        const float4* xr = (const float4*)(x + (size_t)(row0 + row) * DIM) + seg * 2;
        float4 v0 = xr[0], v1 = xr[1];
        __half2 h0 = __floats2half2_rn(v0.x, v0.y), h1 = __floats2half2_rn(v0.z, v0.w);
        __half2 h2 = __floats2half2_rn(v1.x, v1.y), h3 = __floats2half2_rn(v1.z, v1.w);
        uint4 pk = { *(uint32_t*)&h0, *(uint32_t*)&h1, *(uint32_t*)&h2, *(uint32_t*)&h3 };
        *(uint4*)(dynsmem + (row * XSTR + seg * 8) * 2) = pk;
    }
#pragma unroll
    for (int t = 0; t < 8; ++t) {
        int lin = t * 512 + tid;
        int row = lin >> 5, seg = lin & 31;
        cpa16(sb_es + (row * XSTR + seg * 8) * 2,
              g_eh + (size_t)(qcode0 + row) * DIM + seg * 8);
    }
    CP_COMMIT();
#pragma unroll
    for (int t = 0; t < 8; ++t) {
        int lin = t * 512 + tid;
        int row = lin >> 5, seg = lin & 31;
        cpa16(sb_es + ES_BUF_BYTES + (row * XSTR + seg * 8) * 2,
              g_eh + (size_t)(qcode0 + 128 + row) * DIM + seg * 8);
    }
    CP_COMMIT();

    uint32_t a_base[2];
#pragma unroll
    for (int mi = 0; mi < 2; ++mi)
        a_base[mi] = sb_xs + ((warp_m * 32 + mi * 16 + (l & 15)) * XSTR + (l >> 4) * 8) * 2;
    const int bcode = (l & 7) + ((l >> 4) << 3);
    const int bkh   = (l >> 3) & 1;
    uint32_t b_base[2];
#pragma unroll
    for (int bt = 0; bt < 2; ++bt)
        b_base[bt] = sb_es + ((warp_n * 32 + bt * 16 + bcode) * XSTR + bkh * 8) * 2;

    float acc[2][4][4];
#pragma unroll
    for (int mi = 0; mi < 2; ++mi)
#pragma unroll
        for (int ni = 0; ni < 4; ++ni)
#pragma unroll
            for (int r = 0; r < 4; ++r) acc[mi][ni][r] = 0.f;

    float bv[4], sv[4], tv[4];
    int   bi[4], si[4];
#pragma unroll
    for (int r = 0; r < 4; ++r) {
        bv[r] = FLT_MAX; sv[r] = FLT_MAX; tv[r] = FLT_MAX; bi[r] = 0; si[r] = 0;
    }

    for (int c = 0; c < CPQ; ++c) {
        CP_WAIT1();
        __syncthreads();
        const uint32_t bofs = (c & 1) ? ES_BUF_BYTES : 0;

#pragma unroll 4
        for (int kk = 0; kk < 16; ++kk) {
            uint32_t a[2][4], b[2][4];
#pragma unroll
            for (int mi = 0; mi < 2; ++mi)
                ldmx4(a[mi][0], a[mi][1], a[mi][2], a[mi][3], a_base[mi] + kk * 32);
#pragma unroll
            for (int bt = 0; bt < 2; ++bt)
                ldmx4(b[bt][0], b[bt][1], b[bt][2], b[bt][3], b_base[bt] + bofs + kk * 32);
#pragma unroll
            for (int mi = 0; mi < 2; ++mi) {
#pragma unroll
                for (int ni = 0; ni < 4; ++ni) {
                    uint32_t bf[2] = { b[ni >> 1][(ni & 1) * 2], b[ni >> 1][(ni & 1) * 2 + 1] };
                    mma16816(acc[mi][ni], a[mi], bf);
                }
            }
        }

        // ---- epilogue BEFORE the barrier (registers + __ldg only):
        //      fills the slow-warp wait with useful work ----
        const int colbase = qcode0 + c * 128 + warp_n * 32 + (l & 3) * 2;
#pragma unroll
        for (int ni = 0; ni < 4; ++ni) {
            float2 eq = __ldg((const float2*)(g_esq + colbase + ni * 8));
#pragma unroll
            for (int mi = 0; mi < 2; ++mi) {
#pragma unroll
                for (int h = 0; h < 2; ++h) {
                    int r = mi * 2 + h;
                    float d0 = eq.x - 2.0f * acc[mi][ni][h * 2];
                    float d1 = eq.y - 2.0f * acc[mi][ni][h * 2 + 1];
                    acc[mi][ni][h * 2] = 0.f; acc[mi][ni][h * 2 + 1] = 0.f;
                    int code = colbase + ni * 8;
                    ins3(d0, code,     bv[r], sv[r], tv[r], bi[r], si[r]);
                    ins3(d1, code + 1, bv[r], sv[r], tv[r], bi[r], si[r]);
                }
            }
        }

        __syncthreads();
        if (c + 2 < CPQ) {
#pragma unroll
            for (int t = 0; t < 8; ++t) {
                int lin = t * 512 + tid;
                int row = lin >> 5, seg = lin & 31;
                cpa16(sb_es + bofs + (row * XSTR + seg * 8) * 2,
                      g_eh + (size_t)(qcode0 + (c + 2) * 128 + row) * DIM + seg * 8);
            }
        }
        CP_COMMIT();
    }

    // ---- cross-thread top-3 merge (16 owners per row) ----
    float* rb = (float*)(dynsmem + 128 * XSTR * 2);
    float* rs = rb + 2048;
    float* rt = rs + 2048;
    int*   r1 = (int*)(rt + 2048);
    int*   r2 = r1 + 2048;
    __syncthreads();
#pragma unroll
    for (int mi = 0; mi < 2; ++mi)
#pragma unroll
        for (int h = 0; h < 2; ++h) {
            int row  = warp_m * 32 + mi * 16 + (l >> 2) + 8 * h;
            int slot = warp_n * 4 + (l & 3);
            int r = mi * 2 + h;
            rb[row * 16 + slot] = bv[r];
            rs[row * 16 + slot] = sv[r];
            rt[row * 16 + slot] = tv[r];
            r1[row * 16 + slot] = bi[r];
            r2[row * 16 + slot] = si[r];
        }
    __syncthreads();
    if (tid < 128) {
        float b1 = FLT_MAX, s1 = FLT_MAX, t1 = FLT_MAX;
        int i1 = 0, i2 = 0;
#pragma unroll
        for (int t = 0; t < 16; ++t) {
            ins3(rb[tid * 16 + t], r1[tid * 16 + t], b1, s1, t1, i1, i2);
            ins3(rs[tid * 16 + t], r2[tid * 16 + t], b1, s1, t1, i1, i2);
            float t2 = rt[tid * 16 + t];
            if (t2 < t1) t1 = t2;
        }
        int grow = row0 + tid;
        g_pb[q * NTOT + grow] = b1;
        g_ps[q * NTOT + grow] = s1;
        g_pt[q * NTOT + grow] = t1;
        g_pi1[q * NTOT + grow] = i1;
        g_pi2[q * NTOT + grow] = i2;
    }
}

// ---------------------------------------------------------------------------
// merge quarters: global top-3; route to direct / pairwise / full rescue
// ---------------------------------------------------------------------------
__global__ void merge_kernel() {
    int n = blockIdx.x * blockDim.x + threadIdx.x;
    if (n >= NTOT) return;
    float b1 = FLT_MAX, s1 = FLT_MAX, t1 = FLT_MAX;
    int i1 = 0, i2 = 0;
#pragma unroll
    for (int q = 0; q < NQ; ++q) {
        ins3(g_pb[q * NTOT + n], g_pi1[q * NTOT + n], b1, s1, t1, i1, i2);
        ins3(g_ps[q * NTOT + n], g_pi2[q * NTOT + n], b1, s1, t1, i1, i2);
        float t2 = g_pt[q * NTOT + n];
        if (t2 < t1) t1 = t2;
    }
    if (t1 - b1 < MARGIN) {
        int s = atomicAdd(&g_nflag, 1);
        g_flag[s] = n;
        g_bestkey[n] = 0xFFFFFFFFFFFFFFFFull;
    } else if (s1 - b1 < MARGIN) {
        int s = atomicAdd(&g_npair, 1);
        g_pairn[s] = n;
        g_pairc[s] = make_int2(i1, i2);
    } else {
        g_best[n] = i1;
    }
}

// ---------------------------------------------------------------------------
// pairwise exact: one warp per flagged pair, grid-stride over entries
// ---------------------------------------------------------------------------
__global__ __launch_bounds__(256, 1)
void pair_kernel(const float* __restrict__ x, const float* __restrict__ embed) {
    const int np = g_npair;
    int lane = threadIdx.x & 31;
    for (int e = blockIdx.x * 8 + (threadIdx.x >> 5); e < np; e += gridDim.x * 8) {
        int n = g_pairn[e];
        int2 c = g_pairc[e];
        const float4* xr = (const float4*)(x + (size_t)n * DIM) + lane * 2;
        const float4* e1 = (const float4*)(embed + (size_t)c.x * DIM) + lane * 2;
        const float4* e2 = (const float4*)(embed + (size_t)c.y * DIM) + lane * 2;
        float dot1 = 0.f, dot2 = 0.f;
#pragma unroll
        for (int t = 0; t < 2; ++t) {
            float4 xv = xr[t], a = e1[t], b = e2[t];
            dot1 += xv.x * a.x + xv.y * a.y + xv.z * a.z + xv.w * a.w;
            dot2 += xv.x * b.x + xv.y * b.y + xv.z * b.z + xv.w * b.w;
        }
#pragma unroll
        for (int o = 16; o; o >>= 1) {
            dot1 += __shfl_xor_sync(0xffffffffu, dot1, o);
            dot2 += __shfl_xor_sync(0xffffffffu, dot2, o);
        }
        if (lane == 0) {
            float d1 = g_esq[c.x] - 2.0f * dot1;
            float d2 = g_esq[c.y] - 2.0f * dot2;
            int win = (d1 < d2) ? c.x : (d2 < d1) ? c.y : min(c.x, c.y);
            g_best[n] = win;
        }
    }
}

// ---------------------------------------------------------------------------
// full rescue: exact fp32 rescore of flagged rows over 64 code chunks
// grid (8, 64): row-block grid-stride loop (same work, no dead-block sweep)
// ---------------------------------------------------------------------------
#define ESL 33
#define RESCUE_SMEM ((BM*DIM + BN*ESL + BN + BM*16) * 4 + (BM*16) * 4 + BM * 4)

__global__ __launch_bounds__(256, 1)
void rescue_kernel(const float* __restrict__ x, const float* __restrict__ embed) {
    const int nf = g_nflag;
    const int code0 = blockIdx.y * BN;

    float* xs      = (float*)dynsmem;
    float* es      = xs + BM * DIM;
    float* esq_s   = es + BN * ESL;
    float* red_val = esq_s + BN;
    int*   red_idx = (int*)(red_val + BM * 16);
    int*   rows_l  = red_idx + BM * 16;

    const int tid = threadIdx.x;
    const int ty = tid >> 4, tx = tid & 15;

    if (tid < BN) esq_s[tid] = g_esq[code0 + tid];

    for (int base = blockIdx.x * BM; base < nf; base += gridDim.x * BM) {

        if (tid < BM) {
            int s = base + tid;
            rows_l[tid] = g_flag[(s < nf) ? s : base];
        }
        __syncthreads();

#pragma unroll 4
        for (int i = 0; i < 32; ++i) {
            int lin = i * 256 + tid;
            int row = lin >> 6, qd = lin & 63;
            ((float4*)(xs + row * DIM))[qd] =
                ((const float4*)(x + (size_t)rows_l[row] * DIM))[qd];
        }

        float best_val[8]; int best_idx[8];
#pragma unroll
        for (int i = 0; i < 8; ++i) { best_val[i] = FLT_MAX; best_idx[i] = 0; }

        float acc[8][8];
#pragma unroll
        for (int i = 0; i < 8; ++i)
#pragma unroll
            for (int j = 0; j < 8; ++j) acc[i][j] = 0.f;

        for (int cb = 0; cb < DIM / 32; ++cb) {
            __syncthreads();
#pragma unroll
            for (int lgl = 0; lgl < 4; ++lgl) {
                int lin = tid + lgl * 256;
                int col = lin >> 3, qd = lin & 7;
                float4 v = *(const float4*)(embed + (size_t)(code0 + col) * DIM + cb * 32 + qd * 4);
                es[col * ESL + qd * 4 + 0] = v.x;
                es[col * ESL + qd * 4 + 1] = v.y;
                es[col * ESL + qd * 4 + 2] = v.z;
                es[col * ESL + qd * 4 + 3] = v.w;
            }
            __syncthreads();
            const float* xbase = xs + cb * 32;
#pragma unroll
            for (int kk = 0; kk < 32; ++kk) {
                float xr[8], er[8];
#pragma unroll
                for (int i = 0; i < 8; ++i) xr[i] = xbase[(ty + 16 * i) * DIM + kk];
#pragma unroll
                for (int j = 0; j < 8; ++j) er[j] = es[(tx + 16 * j) * ESL + kk];
#pragma unroll
                for (int i = 0; i < 8; ++i)
#pragma unroll
                    for (int j = 0; j < 8; ++j)
                        acc[i][j] = fmaf(xr[i], er[j], acc[i][j]);
            }
        }
#pragma unroll
        for (int j = 0; j < 8; ++j) {
            int code = code0 + tx + 16 * j;
            float esq = esq_s[tx + 16 * j];
#pragma unroll
            for (int i = 0; i < 8; ++i) {
                float d = esq - 2.0f * acc[i][j];
                if (d < best_val[i] || (d == best_val[i] && code < best_idx[i])) {
                    best_val[i] = d; best_idx[i] = code;
                }
            }
        }

        __syncthreads();
#pragma unroll
        for (int i = 0; i < 8; ++i) {
            int r = ty + 16 * i;
            red_val[r * 16 + tx] = best_val[i];
            red_idx[r * 16 + tx] = best_idx[i];
        }
        __syncthreads();
        if (tid < BM) {
            float bvv = red_val[tid * 16];
            int   bii = red_idx[tid * 16];
#pragma unroll
            for (int t = 1; t < 16; ++t) {
                float v = red_val[tid * 16 + t];
                int  ix = red_idx[tid * 16 + t];
                if (v < bvv || (v == bvv && ix < bii)) { bvv = v; bii = ix; }
            }
            atomicMin(&g_bestkey[rows_l[tid]], mkkey(bvv, bii));
        }
        __syncthreads();   // protect rows_l/xs before next iteration
    }
}

__global__ void finalize_kernel() {
    int s = blockIdx.x * blockDim.x + threadIdx.x;
    if (s < g_nflag) {
        int row = g_flag[s];
        g_best[row] = (int)(g_bestkey[row] & 0xffffffffu);
    }
}

// gather: 4 rows per 256-thread block
__global__ void gather_kernel(const float* __restrict__ embed, float* __restrict__ out) {
    int row = blockIdx.x * 4 + (threadIdx.x >> 6);
    int t   = threadIdx.x & 63;
    int idx = g_best[row];
    const float4* src = (const float4*)(embed + (size_t)idx * DIM);
    float4*       dst = (float4*)(out + (size_t)row * DIM);
    dst[t] = src[t];
}

// ---------------------------------------------------------------------------
extern "C" void kernel_launch(void* const* d_in, const int* in_sizes, int n_in,
                              void* d_out, int out_size) {
    const float* x     = (const float*)d_in[0];
    const float* embed = (const float*)d_in[1];
    float*       out   = (float*)d_out;

    cudaFuncSetAttribute(argmin_hmma, cudaFuncAttributeMaxDynamicSharedMemorySize, MAIN_SMEM);
    cudaFuncSetAttribute(rescue_kernel, cudaFuncAttributeMaxDynamicSharedMemorySize, RESCUE_SMEM);

    prep_kernel<<<KCB / 8, 256>>>(embed);
    argmin_hmma<<<dim3(NTOT / BM, NQ), 512, MAIN_SMEM>>>(x);
    merge_kernel<<<NTOT / 256, 256>>>();
    pair_kernel<<<1024, 256>>>(x, embed);
    rescue_kernel<<<dim3(8, KCB / BN), 256, RESCUE_SMEM>>>(x, embed);
    finalize_kernel<<<NTOT / 256, 256>>>();
    gather_kernel<<<NTOT / 4, 256>>>(embed, out);
}

// round 16
// speedup vs baseline: 1.7711x; 1.0930x over previous
#include <cuda_runtime.h>
#include <cuda_fp16.h>
#include <cfloat>
#include <cstdint>

#define DIM   256
#define KCB   8192
#define NTOT  32768
#define BM    128
#define BN    128
#define NQ    4
#define CPQ   16
#define MARGIN 0.25f

#define XSTR  264
#define ES_BUF_BYTES (128 * XSTR * 2)
#define MAIN_SMEM (3 * 128 * XSTR * 2)

// ---------------- device scratch ----------------
__device__ __align__(16) __half g_eh[KCB * DIM];
__device__ float g_esq[KCB];
__device__ int   g_best[NTOT];
__device__ int   g_flag[NTOT];
__device__ unsigned long long g_bestkey[NTOT];
__device__ int   g_nflag;
__device__ int   g_npair;
__device__ int   g_pairn[NTOT];
__device__ int2  g_pairc[NTOT];
__device__ float g_pb[NQ * NTOT];
__device__ float g_ps[NQ * NTOT];
__device__ float g_pt[NQ * NTOT];
__device__ int   g_pi1[NQ * NTOT];
__device__ int   g_pi2[NQ * NTOT];

extern __shared__ char dynsmem[];

__device__ __forceinline__ uint32_t smem_u32(const void* p) {
    uint32_t a;
    asm("{ .reg .u64 t; cvta.to.shared.u64 t, %1; cvt.u32.u64 %0, t; }" : "=r"(a) : "l"(p));
    return a;
}
__device__ __forceinline__ void cpa16(uint32_t dst, const void* src) {
    asm volatile("cp.async.cg.shared.global [%0], [%1], 16;" :: "r"(dst), "l"(src));
}
#define CP_COMMIT() asm volatile("cp.async.commit_group;" ::: "memory")
#define CP_WAIT1()  asm volatile("cp.async.wait_group 1;" ::: "memory")
#define GBAR(id)    asm volatile("bar.sync %0, 128;" :: "r"(id) : "memory")

__device__ __forceinline__ void ldmx4(uint32_t& r0, uint32_t& r1, uint32_t& r2, uint32_t& r3,
                                      uint32_t addr) {
    asm volatile("ldmatrix.sync.aligned.m8n8.x4.shared.b16 {%0,%1,%2,%3}, [%4];"
                 : "=r"(r0), "=r"(r1), "=r"(r2), "=r"(r3) : "r"(addr));
}
__device__ __forceinline__ void mma16816(float* c, const uint32_t* a, const uint32_t* b) {
    asm volatile("mma.sync.aligned.m16n8k16.row.col.f32.f16.f16.f32 "
                 "{%0,%1,%2,%3}, {%4,%5,%6,%7}, {%8,%9}, {%0,%1,%2,%3};"
                 : "+f"(c[0]), "+f"(c[1]), "+f"(c[2]), "+f"(c[3])
                 : "r"(a[0]), "r"(a[1]), "r"(a[2]), "r"(a[3]), "r"(b[0]), "r"(b[1]));
}
__device__ __forceinline__ unsigned long long mkkey(float f, int idx) {
    unsigned u = __float_as_uint(f);
    u = (u & 0x80000000u) ? ~u : (u | 0x80000000u);
    return ((unsigned long long)u << 32) | (unsigned)idx;
}
__device__ __forceinline__ void ins3(float v, int ix,
                                     float& b, float& s, float& t, int& ib, int& is_) {
    if (v < b)      { t = s; s = b; is_ = ib; b = v; ib = ix; }
    else if (v < s) { t = s; s = v; is_ = ix; }
    else if (v < t) { t = v; }
}

// ---------------------------------------------------------------------------
// fused: embed fp32 -> fp16 conversion + |e|^2, one warp per code row
// ---------------------------------------------------------------------------
__global__ void prep_kernel(const float* __restrict__ embed) {
    if (blockIdx.x == 0 && threadIdx.x == 0) { g_nflag = 0; g_npair = 0; }
    int k = blockIdx.x * 8 + (threadIdx.x >> 5);
    if (k >= KCB) return;
    int lane = threadIdx.x & 31;
    const float4* row = (const float4*)(embed + (size_t)k * DIM);
    __half2* dst = (__half2*)(g_eh + (size_t)k * DIM);
    float s = 0.f;
#pragma unroll
    for (int t = 0; t < 2; ++t) {
        float4 v = row[lane + 32 * t];
        s += v.x * v.x + v.y * v.y + v.z * v.z + v.w * v.w;
        dst[(lane + 32 * t) * 2]     = __floats2half2_rn(v.x, v.y);
        dst[(lane + 32 * t) * 2 + 1] = __floats2half2_rn(v.z, v.w);
    }
#pragma unroll
    for (int o = 16; o; o >>= 1) s += __shfl_xor_sync(0xffffffffu, s, o);
    if (lane == 0) g_esq[k] = s;
}

// ---------------------------------------------------------------------------
// main: fp16 mma.sync, group-local staging + named barriers per warp_n group
// ---------------------------------------------------------------------------
__global__ __launch_bounds__(512, 1) void argmin_hmma(const float* __restrict__ x) {
    const uint32_t sb    = smem_u32(dynsmem);
    const uint32_t sb_xs = sb;
    const uint32_t sb_es = sb + 128 * XSTR * 2;

    const int tid = threadIdx.x;
    const int wid = tid >> 5, l = tid & 31;
    const int warp_m = wid >> 2, warp_n = wid & 3;
    const int gbar = 1 + warp_n;                 // named barrier id per group
    const int gt   = warp_m * 32 + l;            // thread index within group [0,128)
    const int row0 = blockIdx.x * BM;
    const int q    = blockIdx.y;
    const int qcode0 = q * (KCB / NQ);

    // ---- prologue: x fp32 -> half (block-wide); es slices 0,1 (group-local) ----
#pragma unroll
    for (int t = 0; t < 8; ++t) {
        int lin = t * 512 + tid;
        int row = lin >> 5, seg = lin & 31;
        const float4* xr = (const float4*)(x + (size_t)(row0 + row) * DIM) + seg * 2;
        float4 v0 = xr[0], v1 = xr[1];
        __half2 h0 = __floats2half2_rn(v0.x, v0.y), h1 = __floats2half2_rn(v0.z, v0.w);
        __half2 h2 = __floats2half2_rn(v1.x, v1.y), h3 = __floats2half2_rn(v1.z, v1.w);
        uint4 pk = { *(uint32_t*)&h0, *(uint32_t*)&h1, *(uint32_t*)&h2, *(uint32_t*)&h3 };
        *(uint4*)(dynsmem + (row * XSTR + seg * 8) * 2) = pk;
    }
    // group g stages rows [g*32, g*32+32) of chunk 0, then chunk 1
#pragma unroll
    for (int t = 0; t < 8; ++t) {
        int lin = t * 128 + gt;                  // 0..1023 = 32 rows x 32 segs
        int row = warp_n * 32 + (lin >> 5), seg = lin & 31;
        cpa16(sb_es + (row * XSTR + seg * 8) * 2,
              g_eh + (size_t)(qcode0 + row) * DIM + seg * 8);
    }
    CP_COMMIT();
#pragma unroll
    for (int t = 0; t < 8; ++t) {
        int lin = t * 128 + gt;
        int row = warp_n * 32 + (lin >> 5), seg = lin & 31;
        cpa16(sb_es + ES_BUF_BYTES + (row * XSTR + seg * 8) * 2,
              g_eh + (size_t)(qcode0 + 128 + row) * DIM + seg * 8);
    }
    CP_COMMIT();
    __syncthreads();                             // xs visible to all groups

    uint32_t a_base[2];
#pragma unroll
    for (int mi = 0; mi < 2; ++mi)
        a_base[mi] = sb_xs + ((warp_m * 32 + mi * 16 + (l & 15)) * XSTR + (l >> 4) * 8) * 2;
    const int bcode = (l & 7) + ((l >> 4) << 3);
    const int bkh   = (l >> 3) & 1;
    uint32_t b_base[2];
#pragma unroll
    for (int bt = 0; bt < 2; ++bt)
        b_base[bt] = sb_es + ((warp_n * 32 + bt * 16 + bcode) * XSTR + bkh * 8) * 2;

    float acc[2][4][4];
#pragma unroll
    for (int mi = 0; mi < 2; ++mi)
#pragma unroll
        for (int ni = 0; ni < 4; ++ni)
#pragma unroll
            for (int r = 0; r < 4; ++r) acc[mi][ni][r] = 0.f;

    float bv[4], sv[4], tv[4];
    int   bi[4], si[4];
#pragma unroll
    for (int r = 0; r < 4; ++r) {
        bv[r] = FLT_MAX; sv[r] = FLT_MAX; tv[r] = FLT_MAX; bi[r] = 0; si[r] = 0;
    }

    for (int c = 0; c < CPQ; ++c) {
        CP_WAIT1();                              // own slice of chunk c arrived
        GBAR(gbar);                              // whole slice visible to group
        const uint32_t bofs = (c & 1) ? ES_BUF_BYTES : 0;

#pragma unroll 4
        for (int kk = 0; kk < 16; ++kk) {
            uint32_t a[2][4], b[2][4];
#pragma unroll
            for (int mi = 0; mi < 2; ++mi)
                ldmx4(a[mi][0], a[mi][1], a[mi][2], a[mi][3], a_base[mi] + kk * 32);
#pragma unroll
            for (int bt = 0; bt < 2; ++bt)
                ldmx4(b[bt][0], b[bt][1], b[bt][2], b[bt][3], b_base[bt] + bofs + kk * 32);
#pragma unroll
            for (int mi = 0; mi < 2; ++mi) {
#pragma unroll
                for (int ni = 0; ni < 4; ++ni) {
                    uint32_t bf[2] = { b[ni >> 1][(ni & 1) * 2], b[ni >> 1][(ni & 1) * 2 + 1] };
                    mma16816(acc[mi][ni], a[mi], bf);
                }
            }
        }

        // ---- epilogue BEFORE the barrier (registers + __ldg only) ----
        const int colbase = qcode0 + c * 128 + warp_n * 32 + (l & 3) * 2;
#pragma unroll
        for (int ni = 0; ni < 4; ++ni) {
            float2 eq = __ldg((const float2*)(g_esq + colbase + ni * 8));
#pragma unroll
            for (int mi = 0; mi < 2; ++mi) {
#pragma unroll
                for (int h = 0; h < 2; ++h) {
                    int r = mi * 2 + h;
                    float d0 = eq.x - 2.0f * acc[mi][ni][h * 2];
                    float d1 = eq.y - 2.0f * acc[mi][ni][h * 2 + 1];
                    acc[mi][ni][h * 2] = 0.f; acc[mi][ni][h * 2 + 1] = 0.f;
                    int code = colbase + ni * 8;
                    ins3(d0, code,     bv[r], sv[r], tv[r], bi[r], si[r]);
                    ins3(d1, code + 1, bv[r], sv[r], tv[r], bi[r], si[r]);
                }
            }
        }

        GBAR(gbar);                              // group done reading buffer bofs
        if (c + 2 < CPQ) {                       // group-local prefetch of slice
#pragma unroll
            for (int t = 0; t < 8; ++t) {
                int lin = t * 128 + gt;
                int row = warp_n * 32 + (lin >> 5), seg = lin & 31;
                cpa16(sb_es + bofs + (row * XSTR + seg * 8) * 2,
                      g_eh + (size_t)(qcode0 + (c + 2) * 128 + row) * DIM + seg * 8);
            }
        }
        CP_COMMIT();
    }

    // ---- cross-thread top-3 merge (16 owners per row) ----
    float* rb = (float*)(dynsmem + 128 * XSTR * 2);
    float* rs = rb + 2048;
    float* rt = rs + 2048;
    int*   r1 = (int*)(rt + 2048);
    int*   r2 = r1 + 2048;
    __syncthreads();
#pragma unroll
    for (int mi = 0; mi < 2; ++mi)
#pragma unroll
        for (int h = 0; h < 2; ++h) {
            int row  = warp_m * 32 + mi * 16 + (l >> 2) + 8 * h;
            int slot = warp_n * 4 + (l & 3);
            int r = mi * 2 + h;
            rb[row * 16 + slot] = bv[r];
            rs[row * 16 + slot] = sv[r];
            rt[row * 16 + slot] = tv[r];
            r1[row * 16 + slot] = bi[r];
            r2[row * 16 + slot] = si[r];
        }
    __syncthreads();
    if (tid < 128) {
        float b1 = FLT_MAX, s1 = FLT_MAX, t1 = FLT_MAX;
        int i1 = 0, i2 = 0;
#pragma unroll
        for (int t = 0; t < 16; ++t) {
            ins3(rb[tid * 16 + t], r1[tid * 16 + t], b1, s1, t1, i1, i2);
            ins3(rs[tid * 16 + t], r2[tid * 16 + t], b1, s1, t1, i1, i2);
            float t2 = rt[tid * 16 + t];
            if (t2 < t1) t1 = t2;
        }
        int grow = row0 + tid;
        g_pb[q * NTOT + grow] = b1;
        g_ps[q * NTOT + grow] = s1;
        g_pt[q * NTOT + grow] = t1;
        g_pi1[q * NTOT + grow] = i1;
        g_pi2[q * NTOT + grow] = i2;
    }
}

// ---------------------------------------------------------------------------
// merge quarters: global top-3; route to direct / pairwise / full rescue
// ---------------------------------------------------------------------------
__global__ void merge_kernel() {
    int n = blockIdx.x * blockDim.x + threadIdx.x;
    if (n >= NTOT) return;
    float b1 = FLT_MAX, s1 = FLT_MAX, t1 = FLT_MAX;
    int i1 = 0, i2 = 0;
#pragma unroll
    for (int q = 0; q < NQ; ++q) {
        ins3(g_pb[q * NTOT + n], g_pi1[q * NTOT + n], b1, s1, t1, i1, i2);
        ins3(g_ps[q * NTOT + n], g_pi2[q * NTOT + n], b1, s1, t1, i1, i2);
        float t2 = g_pt[q * NTOT + n];
        if (t2 < t1) t1 = t2;
    }
    if (t1 - b1 < MARGIN) {
        int s = atomicAdd(&g_nflag, 1);
        g_flag[s] = n;
        g_bestkey[n] = 0xFFFFFFFFFFFFFFFFull;
    } else if (s1 - b1 < MARGIN) {
        int s = atomicAdd(&g_npair, 1);
        g_pairn[s] = n;
        g_pairc[s] = make_int2(i1, i2);
    } else {
        g_best[n] = i1;
    }
}

// ---------------------------------------------------------------------------
// pairwise exact: one warp per flagged pair, grid-stride over entries
// ---------------------------------------------------------------------------
__global__ __launch_bounds__(256, 1)
void pair_kernel(const float* __restrict__ x, const float* __restrict__ embed) {
    const int np = g_npair;
    int lane = threadIdx.x & 31;
    for (int e = blockIdx.x * 8 + (threadIdx.x >> 5); e < np; e += gridDim.x * 8) {
        int n = g_pairn[e];
        int2 c = g_pairc[e];
        const float4* xr = (const float4*)(x + (size_t)n * DIM) + lane * 2;
        const float4* e1 = (const float4*)(embed + (size_t)c.x * DIM) + lane * 2;
        const float4* e2 = (const float4*)(embed + (size_t)c.y * DIM) + lane * 2;
        float dot1 = 0.f, dot2 = 0.f;
#pragma unroll
        for (int t = 0; t < 2; ++t) {
            float4 xv = xr[t], a = e1[t], b = e2[t];
            dot1 += xv.x * a.x + xv.y * a.y + xv.z * a.z + xv.w * a.w;
            dot2 += xv.x * b.x + xv.y * b.y + xv.z * b.z + xv.w * b.w;
        }
#pragma unroll
        for (int o = 16; o; o >>= 1) {
            dot1 += __shfl_xor_sync(0xffffffffu, dot1, o);
            dot2 += __shfl_xor_sync(0xffffffffu, dot2, o);
        }
        if (lane == 0) {
            float d1 = g_esq[c.x] - 2.0f * dot1;
            float d2 = g_esq[c.y] - 2.0f * dot2;
            int win = (d1 < d2) ? c.x : (d2 < d1) ? c.y : min(c.x, c.y);
            g_best[n] = win;
        }
    }
}

// ---------------------------------------------------------------------------
// full rescue: exact fp32 rescore of flagged rows over 64 code chunks
// grid (8, 64): row-block grid-stride loop
// ---------------------------------------------------------------------------
#define ESL 33
#define RESCUE_SMEM ((BM*DIM + BN*ESL + BN + BM*16) * 4 + (BM*16) * 4 + BM * 4)

__global__ __launch_bounds__(256, 1)
void rescue_kernel(const float* __restrict__ x, const float* __restrict__ embed) {
    const int nf = g_nflag;
    const int code0 = blockIdx.y * BN;

    float* xs      = (float*)dynsmem;
    float* es      = xs + BM * DIM;
    float* esq_s   = es + BN * ESL;
    float* red_val = esq_s + BN;
    int*   red_idx = (int*)(red_val + BM * 16);
    int*   rows_l  = red_idx + BM * 16;

    const int tid = threadIdx.x;
    const int ty = tid >> 4, tx = tid & 15;

    if (tid < BN) esq_s[tid] = g_esq[code0 + tid];

    for (int base = blockIdx.x * BM; base < nf; base += gridDim.x * BM) {

        if (tid < BM) {
            int s = base + tid;
            rows_l[tid] = g_flag[(s < nf) ? s : base];
        }
        __syncthreads();

#pragma unroll 4
        for (int i = 0; i < 32; ++i) {
            int lin = i * 256 + tid;
            int row = lin >> 6, qd = lin & 63;
            ((float4*)(xs + row * DIM))[qd] =
                ((const float4*)(x + (size_t)rows_l[row] * DIM))[qd];
        }

        float best_val[8]; int best_idx[8];
#pragma unroll
        for (int i = 0; i < 8; ++i) { best_val[i] = FLT_MAX; best_idx[i] = 0; }

        float acc[8][8];
#pragma unroll
        for (int i = 0; i < 8; ++i)
#pragma unroll
            for (int j = 0; j < 8; ++j) acc[i][j] = 0.f;

        for (int cb = 0; cb < DIM / 32; ++cb) {
            __syncthreads();
#pragma unroll
            for (int lgl = 0; lgl < 4; ++lgl) {
                int lin = tid + lgl * 256;
                int col = lin >> 3, qd = lin & 7;
                float4 v = *(const float4*)(embed + (size_t)(code0 + col) * DIM + cb * 32 + qd * 4);
                es[col * ESL + qd * 4 + 0] = v.x;
                es[col * ESL + qd * 4 + 1] = v.y;
                es[col * ESL + qd * 4 + 2] = v.z;
                es[col * ESL + qd * 4 + 3] = v.w;
            }
            __syncthreads();
            const float* xbase = xs + cb * 32;
#pragma unroll
            for (int kk = 0; kk < 32; ++kk) {
                float xr[8], er[8];
#pragma unroll
                for (int i = 0; i < 8; ++i) xr[i] = xbase[(ty + 16 * i) * DIM + kk];
#pragma unroll
                for (int j = 0; j < 8; ++j) er[j] = es[(tx + 16 * j) * ESL + kk];
#pragma unroll
                for (int i = 0; i < 8; ++i)
#pragma unroll
                    for (int j = 0; j < 8; ++j)
                        acc[i][j] = fmaf(xr[i], er[j], acc[i][j]);
            }
        }
#pragma unroll
        for (int j = 0; j < 8; ++j) {
            int code = code0 + tx + 16 * j;
            float esq = esq_s[tx + 16 * j];
#pragma unroll
            for (int i = 0; i < 8; ++i) {
                float d = esq - 2.0f * acc[i][j];
                if (d < best_val[i] || (d == best_val[i] && code < best_idx[i])) {
                    best_val[i] = d; best_idx[i] = code;
                }
            }
        }

        __syncthreads();
#pragma unroll
        for (int i = 0; i < 8; ++i) {
            int r = ty + 16 * i;
            red_val[r * 16 + tx] = best_val[i];
            red_idx[r * 16 + tx] = best_idx[i];
        }
        __syncthreads();
        if (tid < BM) {
            float bvv = red_val[tid * 16];
            int   bii = red_idx[tid * 16];
#pragma unroll
            for (int t = 1; t < 16; ++t) {
                float v = red_val[tid * 16 + t];
                int  ix = red_idx[tid * 16 + t];
                if (v < bvv || (v == bvv && ix < bii)) { bvv = v; bii = ix; }
            }
            atomicMin(&g_bestkey[rows_l[tid]], mkkey(bvv, bii));
        }
        __syncthreads();
    }
}

__global__ void finalize_kernel() {
    int s = blockIdx.x * blockDim.x + threadIdx.x;
    if (s < g_nflag) {
        int row = g_flag[s];
        g_best[row] = (int)(g_bestkey[row] & 0xffffffffu);
    }
}

// gather: 4 rows per 256-thread block
__global__ void gather_kernel(const float* __restrict__ embed, float* __restrict__ out) {
    int row = blockIdx.x * 4 + (threadIdx.x >> 6);
    int t   = threadIdx.x & 63;
    int idx = g_best[row];
    const float4* src = (const float4*)(embed + (size_t)idx * DIM);
    float4*       dst = (float4*)(out + (size_t)row * DIM);
    dst[t] = src[t];
}

// ---------------------------------------------------------------------------
extern "C" void kernel_launch(void* const* d_in, const int* in_sizes, int n_in,
                              void* d_out, int out_size) {
    const float* x     = (const float*)d_in[0];
    const float* embed = (const float*)d_in[1];
    float*       out   = (float*)d_out;

    cudaFuncSetAttribute(argmin_hmma, cudaFuncAttributeMaxDynamicSharedMemorySize, MAIN_SMEM);
    cudaFuncSetAttribute(rescue_kernel, cudaFuncAttributeMaxDynamicSharedMemorySize, RESCUE_SMEM);

    prep_kernel<<<KCB / 8, 256>>>(embed);
    argmin_hmma<<<dim3(NTOT / BM, NQ), 512, MAIN_SMEM>>>(x);
    merge_kernel<<<NTOT / 256, 256>>>();
    pair_kernel<<<1024, 256>>>(x, embed);
    rescue_kernel<<<dim3(8, KCB / BN), 256, RESCUE_SMEM>>>(x, embed);
    finalize_kernel<<<NTOT / 256, 256>>>();
    gather_kernel<<<NTOT / 4, 256>>>(embed, out);
}

// round 17
// speedup vs baseline: 1.7910x; 1.0113x over previous
#include <cuda_runtime.h>
#include <cuda_fp16.h>
#include <cfloat>
#include <cstdint>

#define DIM   256
#define KCB   8192
#define NTOT  32768
#define BM    128
#define NQ    4
#define CPQ   16
#define MARGIN 0.25f

#define XSTR  264
#define ES_BUF_BYTES (128 * XSTR * 2)
#define MAIN_SMEM (3 * 128 * XSTR * 2)

// rescue tile: 128 rows x 64 codes
#define RBN   64

// ---------------- device scratch ----------------
__device__ __align__(16) __half g_eh[KCB * DIM];
__device__ float g_esq[KCB];
__device__ int   g_best[NTOT];
__device__ int   g_flag[NTOT];
__device__ unsigned long long g_bestkey[NTOT];
__device__ int   g_nflag;
__device__ int   g_npair;
__device__ int   g_pairn[NTOT];
__device__ int2  g_pairc[NTOT];
__device__ float g_pb[NQ * NTOT];
__device__ float g_ps[NQ * NTOT];
__device__ float g_pt[NQ * NTOT];
__device__ int   g_pi1[NQ * NTOT];
__device__ int   g_pi2[NQ * NTOT];

extern __shared__ char dynsmem[];

__device__ __forceinline__ uint32_t smem_u32(const void* p) {
    uint32_t a;
    asm("{ .reg .u64 t; cvta.to.shared.u64 t, %1; cvt.u32.u64 %0, t; }" : "=r"(a) : "l"(p));
    return a;
}
__device__ __forceinline__ void cpa16(uint32_t dst, const void* src) {
    asm volatile("cp.async.cg.shared.global [%0], [%1], 16;" :: "r"(dst), "l"(src));
}
#define CP_COMMIT() asm volatile("cp.async.commit_group;" ::: "memory")
#define CP_WAIT1()  asm volatile("cp.async.wait_group 1;" ::: "memory")
#define GBAR(id)    asm volatile("bar.sync %0, 128;" :: "r"(id) : "memory")

__device__ __forceinline__ void ldmx4(uint32_t& r0, uint32_t& r1, uint32_t& r2, uint32_t& r3,
                                      uint32_t addr) {
    asm volatile("ldmatrix.sync.aligned.m8n8.x4.shared.b16 {%0,%1,%2,%3}, [%4];"
                 : "=r"(r0), "=r"(r1), "=r"(r2), "=r"(r3) : "r"(addr));
}
__device__ __forceinline__ void mma16816(float* c, const uint32_t* a, const uint32_t* b) {
    asm volatile("mma.sync.aligned.m16n8k16.row.col.f32.f16.f16.f32 "
                 "{%0,%1,%2,%3}, {%4,%5,%6,%7}, {%8,%9}, {%0,%1,%2,%3};"
                 : "+f"(c[0]), "+f"(c[1]), "+f"(c[2]), "+f"(c[3])
                 : "r"(a[0]), "r"(a[1]), "r"(a[2]), "r"(a[3]), "r"(b[0]), "r"(b[1]));
}
__device__ __forceinline__ unsigned long long mkkey(float f, int idx) {
    unsigned u = __float_as_uint(f);
    u = (u & 0x80000000u) ? ~u : (u | 0x80000000u);
    return ((unsigned long long)u << 32) | (unsigned)idx;
}
__device__ __forceinline__ void ins3(float v, int ix,
                                     float& b, float& s, float& t, int& ib, int& is_) {
    if (v < b)      { t = s; s = b; is_ = ib; b = v; ib = ix; }
    else if (v < s) { t = s; s = v; is_ = ix; }
    else if (v < t) { t = v; }
}

// ---------------------------------------------------------------------------
// fused: embed fp32 -> fp16 conversion + |e|^2, one warp per code row
// ---------------------------------------------------------------------------
__global__ void prep_kernel(const float* __restrict__ embed) {
    if (blockIdx.x == 0 && threadIdx.x == 0) { g_nflag = 0; g_npair = 0; }
    int k = blockIdx.x * 8 + (threadIdx.x >> 5);
    if (k >= KCB) return;
    int lane = threadIdx.x & 31;
    const float4* row = (const float4*)(embed + (size_t)k * DIM);
    __half2* dst = (__half2*)(g_eh + (size_t)k * DIM);
    float s = 0.f;
#pragma unroll
    for (int t = 0; t < 2; ++t) {
        float4 v = row[lane + 32 * t];
        s += v.x * v.x + v.y * v.y + v.z * v.z + v.w * v.w;
        dst[(lane + 32 * t) * 2]     = __floats2half2_rn(v.x, v.y);
        dst[(lane + 32 * t) * 2 + 1] = __floats2half2_rn(v.z, v.w);
    }
#pragma unroll
    for (int o = 16; o; o >>= 1) s += __shfl_xor_sync(0xffffffffu, s, o);
    if (lane == 0) g_esq[k] = s;
}

// ---------------------------------------------------------------------------
// main: fp16 mma.sync, group-local staging + named barriers per warp_n group
// ---------------------------------------------------------------------------
__global__ __launch_bounds__(512, 1) void argmin_hmma(const float* __restrict__ x) {
    const uint32_t sb    = smem_u32(dynsmem);
    const uint32_t sb_xs = sb;
    const uint32_t sb_es = sb + 128 * XSTR * 2;

    const int tid = threadIdx.x;
    const int wid = tid >> 5, l = tid & 31;
    const int warp_m = wid >> 2, warp_n = wid & 3;
    const int gbar = 1 + warp_n;
    const int gt   = warp_m * 32 + l;
    const int row0 = blockIdx.x * BM;
    const int q    = blockIdx.y;
    const int qcode0 = q * (KCB / NQ);

    // ---- prologue: x fp32 -> half (block-wide); es slices 0,1 (group-local) ----
#pragma unroll
    for (int t = 0; t < 8; ++t) {
        int lin = t * 512 + tid;
        int row = lin >> 5, seg = lin & 31;
        const float4* xr = (const float4*)(x + (size_t)(row0 + row) * DIM) + seg * 2;
        float4 v0 = xr[0], v1 = xr[1];
        __half2 h0 = __floats2half2_rn(v0.x, v0.y), h1 = __floats2half2_rn(v0.z, v0.w);
        __half2 h2 = __floats2half2_rn(v1.x, v1.y), h3 = __floats2half2_rn(v1.z, v1.w);
        uint4 pk = { *(uint32_t*)&h0, *(uint32_t*)&h1, *(uint32_t*)&h2, *(uint32_t*)&h3 };
        *(uint4*)(dynsmem + (row * XSTR + seg * 8) * 2) = pk;
    }
#pragma unroll
    for (int t = 0; t < 8; ++t) {
        int lin = t * 128 + gt;
        int row = warp_n * 32 + (lin >> 5), seg = lin & 31;
        cpa16(sb_es + (row * XSTR + seg * 8) * 2,
              g_eh + (size_t)(qcode0 + row) * DIM + seg * 8);
    }
    CP_COMMIT();
#pragma unroll
    for (int t = 0; t < 8; ++t) {
        int lin = t * 128 + gt;
        int row = warp_n * 32 + (lin >> 5), seg = lin & 31;
        cpa16(sb_es + ES_BUF_BYTES + (row * XSTR + seg * 8) * 2,
              g_eh + (size_t)(qcode0 + 128 + row) * DIM + seg * 8);
    }
    CP_COMMIT();
    __syncthreads();

    uint32_t a_base[2];
#pragma unroll
    for (int mi = 0; mi < 2; ++mi)
        a_base[mi] = sb_xs + ((warp_m * 32 + mi * 16 + (l & 15)) * XSTR + (l >> 4) * 8) * 2;
    const int bcode = (l & 7) + ((l >> 4) << 3);
    const int bkh   = (l >> 3) & 1;
    uint32_t b_base[2];
#pragma unroll
    for (int bt = 0; bt < 2; ++bt)
        b_base[bt] = sb_es + ((warp_n * 32 + bt * 16 + bcode) * XSTR + bkh * 8) * 2;

    float acc[2][4][4];
#pragma unroll
    for (int mi = 0; mi < 2; ++mi)
#pragma unroll
        for (int ni = 0; ni < 4; ++ni)
#pragma unroll
            for (int r = 0; r < 4; ++r) acc[mi][ni][r] = 0.f;

    float bv[4], sv[4], tv[4];
    int   bi[4], si[4];
#pragma unroll
    for (int r = 0; r < 4; ++r) {
        bv[r] = FLT_MAX; sv[r] = FLT_MAX; tv[r] = FLT_MAX; bi[r] = 0; si[r] = 0;
    }

    for (int c = 0; c < CPQ; ++c) {
        CP_WAIT1();
        GBAR(gbar);
        const uint32_t bofs = (c & 1) ? ES_BUF_BYTES : 0;

#pragma unroll 4
        for (int kk = 0; kk < 16; ++kk) {
            uint32_t a[2][4], b[2][4];
#pragma unroll
            for (int mi = 0; mi < 2; ++mi)
                ldmx4(a[mi][0], a[mi][1], a[mi][2], a[mi][3], a_base[mi] + kk * 32);
#pragma unroll
            for (int bt = 0; bt < 2; ++bt)
                ldmx4(b[bt][0], b[bt][1], b[bt][2], b[bt][3], b_base[bt] + bofs + kk * 32);
#pragma unroll
            for (int mi = 0; mi < 2; ++mi) {
#pragma unroll
                for (int ni = 0; ni < 4; ++ni) {
                    uint32_t bf[2] = { b[ni >> 1][(ni & 1) * 2], b[ni >> 1][(ni & 1) * 2 + 1] };
                    mma16816(acc[mi][ni], a[mi], bf);
                }
            }
        }

        // ---- epilogue BEFORE the barrier (registers + __ldg only) ----
        const int colbase = qcode0 + c * 128 + warp_n * 32 + (l & 3) * 2;
#pragma unroll
        for (int ni = 0; ni < 4; ++ni) {
            float2 eq = __ldg((const float2*)(g_esq + colbase + ni * 8));
#pragma unroll
            for (int mi = 0; mi < 2; ++mi) {
#pragma unroll
                for (int h = 0; h < 2; ++h) {
                    int r = mi * 2 + h;
                    float d0 = eq.x - 2.0f * acc[mi][ni][h * 2];
                    float d1 = eq.y - 2.0f * acc[mi][ni][h * 2 + 1];
                    acc[mi][ni][h * 2] = 0.f; acc[mi][ni][h * 2 + 1] = 0.f;
                    int code = colbase + ni * 8;
                    ins3(d0, code,     bv[r], sv[r], tv[r], bi[r], si[r]);
                    ins3(d1, code + 1, bv[r], sv[r], tv[r], bi[r], si[r]);
                }
            }
        }

        GBAR(gbar);
        if (c + 2 < CPQ) {
#pragma unroll
            for (int t = 0; t < 8; ++t) {
                int lin = t * 128 + gt;
                int row = warp_n * 32 + (lin >> 5), seg = lin & 31;
                cpa16(sb_es + bofs + (row * XSTR + seg * 8) * 2,
                      g_eh + (size_t)(qcode0 + (c + 2) * 128 + row) * DIM + seg * 8);
            }
        }
        CP_COMMIT();
    }

    // ---- cross-thread top-3 merge (16 owners per row) ----
    float* rb = (float*)(dynsmem + 128 * XSTR * 2);
    float* rs = rb + 2048;
    float* rt = rs + 2048;
    int*   r1 = (int*)(rt + 2048);
    int*   r2 = r1 + 2048;
    __syncthreads();
#pragma unroll
    for (int mi = 0; mi < 2; ++mi)
#pragma unroll
        for (int h = 0; h < 2; ++h) {
            int row  = warp_m * 32 + mi * 16 + (l >> 2) + 8 * h;
            int slot = warp_n * 4 + (l & 3);
            int r = mi * 2 + h;
            rb[row * 16 + slot] = bv[r];
            rs[row * 16 + slot] = sv[r];
            rt[row * 16 + slot] = tv[r];
            r1[row * 16 + slot] = bi[r];
            r2[row * 16 + slot] = si[r];
        }
    __syncthreads();
    if (tid < 128) {
        float b1 = FLT_MAX, s1 = FLT_MAX, t1 = FLT_MAX;
        int i1 = 0, i2 = 0;
#pragma unroll
        for (int t = 0; t < 16; ++t) {
            ins3(rb[tid * 16 + t], r1[tid * 16 + t], b1, s1, t1, i1, i2);
            ins3(rs[tid * 16 + t], r2[tid * 16 + t], b1, s1, t1, i1, i2);
            float t2 = rt[tid * 16 + t];
            if (t2 < t1) t1 = t2;
        }
        int grow = row0 + tid;
        g_pb[q * NTOT + grow] = b1;
        g_ps[q * NTOT + grow] = s1;
        g_pt[q * NTOT + grow] = t1;
        g_pi1[q * NTOT + grow] = i1;
        g_pi2[q * NTOT + grow] = i2;
    }
}

// ---------------------------------------------------------------------------
// merge quarters: global top-3; route. Full-rescue rows get g_best = -1.
// ---------------------------------------------------------------------------
__global__ void merge_kernel() {
    int n = blockIdx.x * blockDim.x + threadIdx.x;
    if (n >= NTOT) return;
    float b1 = FLT_MAX, s1 = FLT_MAX, t1 = FLT_MAX;
    int i1 = 0, i2 = 0;
#pragma unroll
    for (int q = 0; q < NQ; ++q) {
        ins3(g_pb[q * NTOT + n], g_pi1[q * NTOT + n], b1, s1, t1, i1, i2);
        ins3(g_ps[q * NTOT + n], g_pi2[q * NTOT + n], b1, s1, t1, i1, i2);
        float t2 = g_pt[q * NTOT + n];
        if (t2 < t1) t1 = t2;
    }
    if (t1 - b1 < MARGIN) {
        int s = atomicAdd(&g_nflag, 1);
        g_flag[s] = n;
        g_bestkey[n] = 0xFFFFFFFFFFFFFFFFull;
        g_best[n] = -1;                 // sentinel: resolve from g_bestkey in gather
    } else if (s1 - b1 < MARGIN) {
        int s = atomicAdd(&g_npair, 1);
        g_pairn[s] = n;
        g_pairc[s] = make_int2(i1, i2);
        g_best[n] = i1;                 // overwritten by pair_kernel
    } else {
        g_best[n] = i1;
    }
}

// ---------------------------------------------------------------------------
// pairwise exact: one warp per flagged pair, grid-stride over entries
// ---------------------------------------------------------------------------
__global__ __launch_bounds__(256, 1)
void pair_kernel(const float* __restrict__ x, const float* __restrict__ embed) {
    const int np = g_npair;
    int lane = threadIdx.x & 31;
    for (int e = blockIdx.x * 8 + (threadIdx.x >> 5); e < np; e += gridDim.x * 8) {
        int n = g_pairn[e];
        int2 c = g_pairc[e];
        const float4* xr = (const float4*)(x + (size_t)n * DIM) + lane * 2;
        const float4* e1 = (const float4*)(embed + (size_t)c.x * DIM) + lane * 2;
        const float4* e2 = (const float4*)(embed + (size_t)c.y * DIM) + lane * 2;
        float dot1 = 0.f, dot2 = 0.f;
#pragma unroll
        for (int t = 0; t < 2; ++t) {
            float4 xv = xr[t], a = e1[t], b = e2[t];
            dot1 += xv.x * a.x + xv.y * a.y + xv.z * a.z + xv.w * a.w;
            dot2 += xv.x * b.x + xv.y * b.y + xv.z * b.z + xv.w * b.w;
        }
#pragma unroll
        for (int o = 16; o; o >>= 1) {
            dot1 += __shfl_xor_sync(0xffffffffu, dot1, o);
            dot2 += __shfl_xor_sync(0xffffffffu, dot2, o);
        }
        if (lane == 0) {
            float d1 = g_esq[c.x] - 2.0f * dot1;
            float d2 = g_esq[c.y] - 2.0f * dot2;
            int win = (d1 < d2) ? c.x : (d2 < d1) ? c.y : min(c.x, c.y);
            g_best[n] = win;
        }
    }
}

// ---------------------------------------------------------------------------
// full rescue: exact fp32 rescore of flagged rows over 128 code chunks (64 wide)
// grid (8, 128): row-block grid-stride loop
// ---------------------------------------------------------------------------
#define ESL 33
#define RESCUE_SMEM ((BM*DIM + RBN*ESL + RBN + BM*16) * 4 + (BM*16) * 4 + BM * 4)

__global__ __launch_bounds__(256, 1)
void rescue_kernel(const float* __restrict__ x, const float* __restrict__ embed) {
    const int nf = g_nflag;
    const int code0 = blockIdx.y * RBN;

    float* xs      = (float*)dynsmem;
    float* es      = xs + BM * DIM;
    float* esq_s   = es + RBN * ESL;
    float* red_val = esq_s + RBN;
    int*   red_idx = (int*)(red_val + BM * 16);
    int*   rows_l  = red_idx + BM * 16;

    const int tid = threadIdx.x;
    const int ty = tid >> 4, tx = tid & 15;

    if (tid < RBN) esq_s[tid] = g_esq[code0 + tid];

    for (int base = blockIdx.x * BM; base < nf; base += gridDim.x * BM) {

        if (tid < BM) {
            int s = base + tid;
            rows_l[tid] = g_flag[(s < nf) ? s : base];
        }
        __syncthreads();

#pragma unroll 4
        for (int i = 0; i < 32; ++i) {
            int lin = i * 256 + tid;
            int row = lin >> 6, qd = lin & 63;
            ((float4*)(xs + row * DIM))[qd] =
                ((const float4*)(x + (size_t)rows_l[row] * DIM))[qd];
        }

        float best_val[8]; int best_idx[8];
#pragma unroll
        for (int i = 0; i < 8; ++i) { best_val[i] = FLT_MAX; best_idx[i] = 0; }

        // 8 rows x 4 cols per thread (ty: 16 row groups, tx: 16 col groups of 4)
        float acc[8][4];
#pragma unroll
        for (int i = 0; i < 8; ++i)
#pragma unroll
            for (int j = 0; j < 4; ++j) acc[i][j] = 0.f;

        for (int cb = 0; cb < DIM / 32; ++cb) {
            __syncthreads();
            // stage es: 64 codes x 32 dims
#pragma unroll
            for (int lgl = 0; lgl < 2; ++lgl) {
                int lin = tid + lgl * 256;
                int col = lin >> 3, qd = lin & 7;
                float4 v = *(const float4*)(embed + (size_t)(code0 + col) * DIM + cb * 32 + qd * 4);
                es[col * ESL + qd * 4 + 0] = v.x;
                es[col * ESL + qd * 4 + 1] = v.y;
                es[col * ESL + qd * 4 + 2] = v.z;
                es[col * ESL + qd * 4 + 3] = v.w;
            }
            __syncthreads();
            const float* xbase = xs + cb * 32;
#pragma unroll
            for (int kk = 0; kk < 32; ++kk) {
                float xr[8], er[4];
#pragma unroll
                for (int i = 0; i < 8; ++i) xr[i] = xbase[(ty + 16 * i) * DIM + kk];
#pragma unroll
                for (int j = 0; j < 4; ++j) er[j] = es[(tx + 16 * j) * ESL + kk];
#pragma unroll
                for (int i = 0; i < 8; ++i)
#pragma unroll
                    for (int j = 0; j < 4; ++j)
                        acc[i][j] = fmaf(xr[i], er[j], acc[i][j]);
            }
        }
#pragma unroll
        for (int j = 0; j < 4; ++j) {
            int code = code0 + tx + 16 * j;
            float esq = esq_s[tx + 16 * j];
#pragma unroll
            for (int i = 0; i < 8; ++i) {
                float d = esq - 2.0f * acc[i][j];
                if (d < best_val[i] || (d == best_val[i] && code < best_idx[i])) {
                    best_val[i] = d; best_idx[i] = code;
                }
            }
        }

        __syncthreads();
#pragma unroll
        for (int i = 0; i < 8; ++i) {
            int r = ty + 16 * i;
            red_val[r * 16 + tx] = best_val[i];
            red_idx[r * 16 + tx] = best_idx[i];
        }
        __syncthreads();
        if (tid < BM) {
            float bvv = red_val[tid * 16];
            int   bii = red_idx[tid * 16];
#pragma unroll
            for (int t = 1; t < 16; ++t) {
                float v = red_val[tid * 16 + t];
                int  ix = red_idx[tid * 16 + t];
                if (v < bvv || (v == bvv && ix < bii)) { bvv = v; bii = ix; }
            }
            atomicMin(&g_bestkey[rows_l[tid]], mkkey(bvv, bii));
        }
        __syncthreads();
    }
}

// gather: 4 rows per 256-thread block; resolves full-rescue sentinel inline
__global__ void gather_kernel(const float* __restrict__ embed, float* __restrict__ out) {
    int row = blockIdx.x * 4 + (threadIdx.x >> 6);
    int t   = threadIdx.x & 63;
    int idx = g_best[row];
    if (idx < 0) idx = (int)(g_bestkey[row] & 0xffffffffu);
    const float4* src = (const float4*)(embed + (size_t)idx * DIM);
    float4*       dst = (float4*)(out + (size_t)row * DIM);
    dst[t] = src[t];
}

// ---------------------------------------------------------------------------
extern "C" void kernel_launch(void* const* d_in, const int* in_sizes, int n_in,
                              void* d_out, int out_size) {
    const float* x     = (const float*)d_in[0];
    const float* embed = (const float*)d_in[1];
    float*       out   = (float*)d_out;

    cudaFuncSetAttribute(argmin_hmma, cudaFuncAttributeMaxDynamicSharedMemorySize, MAIN_SMEM);
    cudaFuncSetAttribute(rescue_kernel, cudaFuncAttributeMaxDynamicSharedMemorySize, RESCUE_SMEM);

    prep_kernel<<<KCB / 8, 256>>>(embed);
    argmin_hmma<<<dim3(NTOT / BM, NQ), 512, MAIN_SMEM>>>(x);
    merge_kernel<<<NTOT / 256, 256>>>();
    pair_kernel<<<256, 256>>>(x, embed);
    rescue_kernel<<<dim3(8, KCB / RBN), 256, RESCUE_SMEM>>>(x, embed);
    gather_kernel<<<NTOT / 4, 256>>>(embed, out);
}